// round 12
// baseline (speedup 1.0000x reference)
#include <cuda_runtime.h>
#include <cuda_fp16.h>
#include <math.h>
#include <stdint.h>

// ---------------------------------------------------------------------------
// attention_83932250898666 : B=4, N=2048, D=1024
// d_out layout (float32):
//   [0, 16777216)        out   = concat(x, LN(x+att))   [B,N,2D]
//   [16777216, 25165824) att_score                      [B,N,D]
//   [25165824, 41943040) weight = softmax(QK^T/32)      [B,N,N]
// GEMMs: single-pass fp16 mma.sync (HMMA), fp32 accumulate.
// Round 12: B-fragment TRIPLE buffer (2-slot prefetch lead), pointer-folded
//           prefetch offsets. Everything else identical to round 11.
// ---------------------------------------------------------------------------

#define Bb 4
#define Nn 2048
#define Dd 1024
#define MT (Bb*Nn)   // 8192

// ------------------------- device scratch (no allocs) ----------------------
__device__ __half g_x16[(size_t)MT * Dd];
__device__ __half g_W16[(size_t)3 * Dd * Dd];      // [z][n][k] transposed weights
__device__ float  g_b[2 * Dd];                     // biases q,k
__device__ __half g_QK[(size_t)2 * MT * Dd];       // Q | K
__device__ __half g_Vt[(size_t)MT * Dd];           // per-batch V^T [b][d][n]
__device__ __half g_w16[(size_t)Bb * Nn * Nn];     // softmax weights fp16

// ------------------------------ PTX helpers --------------------------------
__device__ __forceinline__ uint32_t smem_u32(const void* p) {
    uint32_t a;
    asm("{ .reg .u64 t; cvta.to.shared.u64 t, %1; cvt.u32.u64 %0, t; }" : "=r"(a) : "l"(p));
    return a;
}

#define CP16(dst, src) \
    asm volatile("cp.async.cg.shared.global [%0], [%1], 16;" :: "r"(dst), "l"(src))
#define CP_COMMIT() asm volatile("cp.async.commit_group;" ::: "memory")
#define CP_WAIT1()  asm volatile("cp.async.wait_group 1;" ::: "memory")

#define LDSM4(R0, R1, R2, R3, A) \
    asm volatile("ldmatrix.sync.aligned.m8n8.x4.shared.b16 {%0,%1,%2,%3}, [%4];" \
                 : "=r"(R0), "=r"(R1), "=r"(R2), "=r"(R3) : "r"(A))

#define MMAH(D, A0, A1, A2, A3, B0, B1) \
    asm volatile("mma.sync.aligned.m16n8k16.row.col.f32.f16.f16.f32 " \
                 "{%0,%1,%2,%3},{%4,%5,%6,%7},{%8,%9},{%0,%1,%2,%3};" \
                 : "+f"((D)[0]), "+f"((D)[1]), "+f"((D)[2]), "+f"((D)[3]) \
                 : "r"(A0), "r"(A1), "r"(A2), "r"(A3), "r"(B0), "r"(B1))

// ------------------------------- MMA GEMM ----------------------------------
// C[M,N] = alpha*(A @ Bmat^T)(+bias). A:[M,K] fp16 (ld=K), Bmat:[N,K] fp16 (ld=K).
// Block 128x128, 8 warps (4m x 2n), warp tile 32x64, K-chunk 64, 3-stage cp.async.
#define BMm 128
#define BNm 128
#define BKm 64
#define LDSm 72                          // padded row length in halves (144B)
#define OPA (128 * LDSm * 2)             // 18432 B
#define STGB (2 * OPA)                   // 36864 B
#define NSTAGE 3
#define SMEM_BYTES (NSTAGE * STGB)       // 110592

// EPI: 0 fp32 out, 1 fp16 out.  BIASMODE: 0 none, 1 per-col, 2 per-row.
template<int EPI, int BIASMODE>
__global__ __launch_bounds__(256, 2)
void mma_gemm(const __half* __restrict__ A, const __half* __restrict__ B,
              const float* __restrict__ bias,
              float* __restrict__ Cf, __half* __restrict__ Ch,
              int K, int ldc,
              long long sA, long long sB, long long sC, long long sBias, float alpha)
{
    extern __shared__ char smem[];
    const uint32_t sbase = smem_u32(smem);
    const int tid  = threadIdx.x;
    const int wid  = tid >> 5;
    const int lane = tid & 31;
    const int wy = wid >> 1;            // 0..3  (m, 32 rows each)
    const int wx = wid & 1;             // 0..1  (n, 64 cols each)
    const int m0 = blockIdx.y * BMm;
    const int n0 = blockIdx.x * BNm;
    A += (long long)blockIdx.z * sA;
    B += (long long)blockIdx.z * sB;
    if (BIASMODE) bias += (long long)blockIdx.z * sBias;

    float acc[2][8][4];
#pragma unroll
    for (int i = 0; i < 2; i++)
#pragma unroll
        for (int j = 0; j < 8; j++)
#pragma unroll
            for (int q = 0; q < 4; q++) acc[i][j][q] = 0.0f;

    const int nch = K / BKm;

    // hoisted per-thread gmem pointers and smem store offset for cp.async
    const int rA = tid >> 3, cA = tid & 7;
    const __half* gA = A + (long long)(m0 + rA) * K + cA * 8;
    const __half* gB = B + (long long)(n0 + rA) * K + cA * 8;
    const uint32_t soff = (uint32_t)(rA * LDSm + cA * 8) * 2;
    const long long gstep = (long long)32 * K;                 // 32 rows

    // full-stage load (prologue only)
    auto load_stage = [&](uint32_t sb, int k0) {
#pragma unroll
        for (int t = 0; t < 4; t++)
            CP16(sb + soff + t * (32 * LDSm * 2), gA + t * gstep + k0);
#pragma unroll
        for (int t = 0; t < 4; t++)
            CP16(sb + OPA + soff + t * (32 * LDSm * 2), gB + t * gstep + k0);
    };

    // 1/8th of a stage load from pre-advanced pointers; p in [0,8)
    auto load_part = [&](uint32_t sb, const __half* a, const __half* b, int p) {
        if (p < 4)
            CP16(sb + soff + p * (32 * LDSm * 2), a + p * gstep);
        else
            CP16(sb + OPA + soff + (p - 4) * (32 * LDSm * 2), b + (p - 4) * gstep);
    };

    load_stage(sbase, 0);           CP_COMMIT();
    load_stage(sbase + STGB, BKm);  CP_COMMIT();

    // prefetch pointers for chunk c+2
    const __half* gApf = gA + 2 * BKm;
    const __half* gBpf = gB + 2 * BKm;

    // ldmatrix lane base addresses (smem-stage-relative)
    const int arow = (lane & 7) + ((lane >> 3) & 1) * 8;   // 0..15
    const int acol = (lane >> 4) * 8;                      // 0 / 8
    const int brow = (lane & 7) + (lane >> 4) * 8;
    const int bcol = ((lane >> 3) & 1) * 8;
    const uint32_t baseA = (uint32_t)((32 * wy + arow) * LDSm + acol) * 2;
    const uint32_t baseB = (uint32_t)((64 * wx + brow) * LDSm + bcol) * 2 + OPA;

    uint32_t af[2][2][4];      // A fragments, double buffered over ks
    uint32_t bf[3][4][2];      // B fragments, TRIPLE rolling buffer (2-slot lead)

    auto ldA = [&](int buf, uint32_t sb, int ks) {
#pragma unroll
        for (int i = 0; i < 2; i++) {
            uint32_t aoff = sb + baseA + (uint32_t)(16 * i * LDSm + ks * 16) * 2;
            LDSM4(af[buf][i][0], af[buf][i][1], af[buf][i][2], af[buf][i][3], aoff);
        }
    };
    auto ldB = [&](int buf, uint32_t sb, int ks, int jh) {
#pragma unroll
        for (int jpp = 0; jpp < 2; jpp++) {
            uint32_t boff = sb + baseB
                          + (uint32_t)(16 * (2 * jh + jpp) * LDSm + ks * 16) * 2;
            LDSM4(bf[buf][2*jpp][0], bf[buf][2*jpp][1], bf[buf][2*jpp+1][0], bf[buf][2*jpp+1][1],
                  boff);
        }
    };

    uint32_t sb_cur = sbase;                  // stage for chunk c
    uint32_t sb_pf  = sbase + 2 * STGB;       // stage for chunk c+2

    for (int c = 0; c < nch; c++) {
        CP_WAIT1();
        __syncthreads();
        const uint32_t sb = sb_cur;
        const bool pf = (c + 2 < nch);
        const uint32_t s2 = sb_pf;

        ldA(0, sb, 0);
        ldB(0, sb, 0, 0);      // slot 0
        ldB(1, sb, 0, 1);      // slot 1
#pragma unroll
        for (int idx = 0; idx < 8; idx++) {          // ks = idx>>1, jh = idx&1
            const int ks = idx >> 1, jh = idx & 1;
            if (idx < 6) ldB((idx + 2) % 3, sb, (idx + 2) >> 1, (idx + 2) & 1);
            if (jh == 0 && ks < 3) ldA((ks + 1) & 1, sb, ks + 1);
            if (pf) load_part(s2, gApf, gBpf, idx);
            const int ab = ks & 1, bb = idx % 3;
#pragma unroll
            for (int i = 0; i < 2; i++)
#pragma unroll
                for (int jj = 0; jj < 4; jj++)
                    MMAH(acc[i][jh * 4 + jj],
                         af[ab][i][0], af[ab][i][1], af[ab][i][2], af[ab][i][3],
                         bf[bb][jj][0], bf[bb][jj][1]);
        }
        CP_COMMIT();
        // rotate stage pointers (no modulo) and advance prefetch pointers
        sb_cur += STGB; if (sb_cur == sbase + NSTAGE * STGB) sb_cur = sbase;
        sb_pf  += STGB; if (sb_pf  == sbase + NSTAGE * STGB) sb_pf  = sbase;
        gApf += BKm;
        gBpf += BKm;
    }

    // ------------------------------ epilogue --------------------------------
    const int g  = lane >> 2;
    const int t4 = lane & 3;
    const long long cb = (long long)blockIdx.z * sC;
#pragma unroll
    for (int i = 0; i < 2; i++) {
#pragma unroll
        for (int j = 0; j < 8; j++) {
            int mrow = m0 + 32 * wy + 16 * i + g;
            int ncol = n0 + 64 * wx + 8 * j + 2 * t4;
            float v00 = acc[i][j][0] * alpha, v01 = acc[i][j][1] * alpha;
            float v10 = acc[i][j][2] * alpha, v11 = acc[i][j][3] * alpha;
            long long o0 = cb + (long long)mrow * ldc + ncol;
            long long o1 = cb + (long long)(mrow + 8) * ldc + ncol;
            if (BIASMODE == 1) {
                float b0 = bias[ncol], b1 = bias[ncol + 1];
                v00 += b0; v01 += b1; v10 += b0; v11 += b1;
            } else if (BIASMODE == 2) {
                float br0 = bias[mrow], br1 = bias[mrow + 8];
                v00 += br0; v01 += br0; v10 += br1; v11 += br1;
            }
            if (EPI == 0) {
                *(float2*)(Cf + o0) = make_float2(v00, v01);
                *(float2*)(Cf + o1) = make_float2(v10, v11);
            } else {
                *(__half2*)(Ch + o0) = __floats2half2_rn(v00, v01);
                *(__half2*)(Ch + o1) = __floats2half2_rn(v10, v11);
            }
        }
    }
}

// --------------------------- aux kernels ------------------------------------
// fp32 -> fp16 AND copy x into out[:, 0:D] (concat first half, off critical path)
__global__ void cvt_x(const float* __restrict__ in, __half* __restrict__ out16,
                      float* __restrict__ outx)
{
    long long i = ((long long)blockIdx.x * blockDim.x + threadIdx.x) * 4;
    float4 v = *(const float4*)(in + i);
    *(__half2*)(out16 + i)     = __floats2half2_rn(v.x, v.y);
    *(__half2*)(out16 + i + 2) = __floats2half2_rn(v.z, v.w);
    long long row = i >> 10;              // / Dd
    long long col = i & (Dd - 1);
    *(float4*)(outx + row * (2 * Dd) + col) = v;
}

__global__ void copy_bias(const float* __restrict__ b0, const float* __restrict__ b1,
                          float* __restrict__ dst)
{
    int z = blockIdx.x;
    const float* s = (z == 0) ? b0 : b1;
    dst[z * Dd + threadIdx.x] = s[threadIdx.x];
}

// Wt[n,k] = W[k,n] fp16 ; z selects which W
__global__ void transW(const float* __restrict__ W0, const float* __restrict__ W1,
                       const float* __restrict__ W2, __half* __restrict__ out)
{
    __shared__ float t[32][33];
    const float* W = (blockIdx.z == 0) ? W0 : (blockIdx.z == 1) ? W1 : W2;
    __half* o = out + (size_t)blockIdx.z * Dd * Dd;
    int bx = blockIdx.x * 32, by = blockIdx.y * 32;
    int tx = threadIdx.x, ty = threadIdx.y;
#pragma unroll
    for (int r = 0; r < 4; r++)
        t[ty + 8 * r][tx] = W[(long long)(by + ty + 8 * r) * Dd + bx + tx];
    __syncthreads();
#pragma unroll
    for (int r = 0; r < 4; r++)
        o[(long long)(bx + ty + 8 * r) * Dd + by + tx] = __float2half_rn(t[tx][ty + 8 * r]);
}

// single-read row softmax: values held in registers; writes fp32 + fp16
__global__ void softmax_split(float* __restrict__ W, __half* __restrict__ wh)
{
    long long row = blockIdx.x;
    float* p = W + row * (long long)Nn;
    __half* ph = wh + row * (long long)Nn;
    __shared__ float red[8];
    const int tid = threadIdx.x;
    const int lane = tid & 31, warp = tid >> 5;

    float e[8];
    {
        float4 v0 = *(const float4*)(p + tid * 8);
        float4 v1 = *(const float4*)(p + tid * 8 + 4);
        e[0]=v0.x; e[1]=v0.y; e[2]=v0.z; e[3]=v0.w;
        e[4]=v1.x; e[5]=v1.y; e[6]=v1.z; e[7]=v1.w;
    }
    float mx = e[0];
#pragma unroll
    for (int i = 1; i < 8; i++) mx = fmaxf(mx, e[i]);
#pragma unroll
    for (int s = 16; s > 0; s >>= 1)
        mx = fmaxf(mx, __shfl_xor_sync(0xffffffffu, mx, s));
    if (lane == 0) red[warp] = mx;
    __syncthreads();
    mx = red[0];
#pragma unroll
    for (int w = 1; w < 8; w++) mx = fmaxf(mx, red[w]);
    __syncthreads();

    float sum = 0.0f;
#pragma unroll
    for (int i = 0; i < 8; i++) { e[i] = expf(e[i] - mx); sum += e[i]; }
#pragma unroll
    for (int s = 16; s > 0; s >>= 1)
        sum += __shfl_xor_sync(0xffffffffu, sum, s);
    if (lane == 0) red[warp] = sum;
    __syncthreads();
    sum = red[0];
#pragma unroll
    for (int w = 1; w < 8; w++) sum += red[w];
    float inv = 1.0f / sum;

    float4 o0, o1;
    o0.x = e[0]*inv; o0.y = e[1]*inv; o0.z = e[2]*inv; o0.w = e[3]*inv;
    o1.x = e[4]*inv; o1.y = e[5]*inv; o1.z = e[6]*inv; o1.w = e[7]*inv;
    *(float4*)(p + tid * 8)     = o0;
    *(float4*)(p + tid * 8 + 4) = o1;
    *(__half2*)(ph + tid * 8)     = __floats2half2_rn(o0.x, o0.y);
    *(__half2*)(ph + tid * 8 + 2) = __floats2half2_rn(o0.z, o0.w);
    *(__half2*)(ph + tid * 8 + 4) = __floats2half2_rn(o1.x, o1.y);
    *(__half2*)(ph + tid * 8 + 6) = __floats2half2_rn(o1.z, o1.w);
}

// residual + layernorm; writes only out[:, D:2D] (x half written by cvt_x)
__global__ void ln_concat(const float* __restrict__ x, const float* __restrict__ att,
                          const float* __restrict__ gamma, const float* __restrict__ beta,
                          float* __restrict__ out)
{
    long long row = blockIdx.x;
    const float* xr = x + row * Dd;
    const float* ar = att + row * Dd;
    float* o = out + row * (2 * Dd);
    __shared__ float red[256];
    int tid = threadIdx.x;

    float h[4], s = 0.0f;
#pragma unroll
    for (int i = 0; i < 4; i++) { int c = tid + i * 256; h[i] = xr[c] + ar[c]; s += h[i]; }
    red[tid] = s; __syncthreads();
#pragma unroll
    for (int st = 128; st > 0; st >>= 1) {
        if (tid < st) red[tid] += red[tid + st];
        __syncthreads();
    }
    float mu = red[0] * (1.0f / Dd); __syncthreads();

    float v = 0.0f;
#pragma unroll
    for (int i = 0; i < 4; i++) { float d = h[i] - mu; v += d * d; }
    red[tid] = v; __syncthreads();
#pragma unroll
    for (int st = 128; st > 0; st >>= 1) {
        if (tid < st) red[tid] += red[tid + st];
        __syncthreads();
    }
    float rstd = rsqrtf(red[0] * (1.0f / Dd) + 1e-5f);
#pragma unroll
    for (int i = 0; i < 4; i++) {
        int c = tid + i * 256;
        o[Dd + c] = (h[i] - mu) * rstd * gamma[c] + beta[c];
    }
}

// ------------------------------- launcher -----------------------------------
extern "C" void kernel_launch(void* const* d_in, const int* in_sizes, int n_in,
                              void* d_out, int out_size)
{
    const float* x     = (const float*)d_in[0];
    const float* Wk    = (const float*)d_in[1];
    const float* bk    = (const float*)d_in[2];
    const float* Wq    = (const float*)d_in[3];
    const float* bq    = (const float*)d_in[4];
    const float* Wv    = (const float*)d_in[5];
    const float* bv    = (const float*)d_in[6];
    const float* gamma = (const float*)d_in[7];
    const float* beta  = (const float*)d_in[8];

    float* out = (float*)d_out;
    float* att = out + (long long)MT * 2 * Dd;
    float* wgt = att + (long long)MT * Dd;

    __half *x16, *W16, *QK, *Vt, *w16;
    float* bqk;
    cudaGetSymbolAddress((void**)&x16, g_x16);
    cudaGetSymbolAddress((void**)&W16, g_W16);
    cudaGetSymbolAddress((void**)&bqk, g_b);
    cudaGetSymbolAddress((void**)&QK,  g_QK);
    cudaGetSymbolAddress((void**)&Vt,  g_Vt);
    cudaGetSymbolAddress((void**)&w16, g_w16);

    cudaFuncSetAttribute(mma_gemm<0, 0>, cudaFuncAttributeMaxDynamicSharedMemorySize, SMEM_BYTES);
    cudaFuncSetAttribute(mma_gemm<1, 1>, cudaFuncAttributeMaxDynamicSharedMemorySize, SMEM_BYTES);
    cudaFuncSetAttribute(mma_gemm<1, 2>, cudaFuncAttributeMaxDynamicSharedMemorySize, SMEM_BYTES);

    // 1) precision conversions (+ concat x half)
    cvt_x<<<MT * Dd / 4096, 1024>>>(x, x16, out);
    copy_bias<<<2, Dd>>>(bq, bk, bqk);
    {
        dim3 g(Dd / 32, Dd / 32, 3), b(32, 8);
        transW<<<g, b>>>(Wq, Wk, Wv, W16);
    }

    // 2) fused Q,K projection: z in {Q,K}
    {
        dim3 g(Dd / BNm, MT / BMm, 2), b(256);
        mma_gemm<1, 1><<<g, b, SMEM_BYTES>>>(x16, W16, bqk, nullptr, QK,
                                             Dd, Dd,
                                             0, (long long)Dd * Dd, (long long)MT * Dd,
                                             Dd, 1.0f);
    }

    // 3) Vt[b][d,n] = Wv^T @ x_b^T + bv (bias per row) -> fp16, per batch
    {
        dim3 g(Nn / BNm, Dd / BMm, Bb), b(256);
        mma_gemm<1, 2><<<g, b, SMEM_BYTES>>>(W16 + (size_t)2 * Dd * Dd, x16, bv,
                                             nullptr, Vt,
                                             Dd, Nn,
                                             0, (long long)Nn * Dd, (long long)Dd * Nn,
                                             0, 1.0f);
    }

    // 4) scores = Q @ K^T / 32 -> wgt (fp32)
    {
        dim3 g(Nn / BNm, Nn / BMm, Bb), b(256);
        mma_gemm<0, 0><<<g, b, SMEM_BYTES>>>(QK, QK + (size_t)MT * Dd, nullptr,
                                             wgt, nullptr,
                                             Dd, Nn,
                                             (long long)Nn * Dd, (long long)Nn * Dd,
                                             (long long)Nn * Nn, 0, 1.0f / 32.0f);
    }

    // 5) softmax rows in place + fp16 copy (single gmem read)
    softmax_split<<<Bb * Nn, 256>>>(wgt, w16);

    // 6) att = weight @ V -> att (fp32)
    {
        dim3 g(Dd / BNm, Nn / BMm, Bb), b(256);
        mma_gemm<0, 0><<<g, b, SMEM_BYTES>>>(w16, Vt, nullptr, att, nullptr,
                                             Nn, Dd,
                                             (long long)Nn * Nn, (long long)Nn * Dd,
                                             (long long)Nn * Dd, 0, 1.0f);
    }

    // 7) out[:, D:2D] = LN(x + att)
    ln_concat<<<Bb * Nn, 256>>>(x, att, gamma, beta, out);
}

// round 13
// speedup vs baseline: 1.0805x; 1.0805x over previous
#include <cuda_runtime.h>
#include <cuda_fp16.h>
#include <math.h>
#include <stdint.h>

// ---------------------------------------------------------------------------
// attention_83932250898666 : B=4, N=2048, D=1024
// d_out layout (float32):
//   [0, 16777216)        out   = concat(x, LN(x+att))   [B,N,2D]
//   [16777216, 25165824) att_score                      [B,N,D]
//   [25165824, 41943040) weight = softmax(QK^T/32)      [B,N,N]
// GEMMs: single-pass fp16 mma.sync (HMMA), fp32 accumulate.
// Round 13: round-11 GEMM verbatim (2-buffer rolling pipeline — round-12
//           triple-buffer regressed, reverted); warp-shuffle ln_concat.
// ---------------------------------------------------------------------------

#define Bb 4
#define Nn 2048
#define Dd 1024
#define MT (Bb*Nn)   // 8192

// ------------------------- device scratch (no allocs) ----------------------
__device__ __half g_x16[(size_t)MT * Dd];
__device__ __half g_W16[(size_t)3 * Dd * Dd];      // [z][n][k] transposed weights
__device__ float  g_b[2 * Dd];                     // biases q,k
__device__ __half g_QK[(size_t)2 * MT * Dd];       // Q | K
__device__ __half g_Vt[(size_t)MT * Dd];           // per-batch V^T [b][d][n]
__device__ __half g_w16[(size_t)Bb * Nn * Nn];     // softmax weights fp16

// ------------------------------ PTX helpers --------------------------------
__device__ __forceinline__ uint32_t smem_u32(const void* p) {
    uint32_t a;
    asm("{ .reg .u64 t; cvta.to.shared.u64 t, %1; cvt.u32.u64 %0, t; }" : "=r"(a) : "l"(p));
    return a;
}

#define CP16(dst, src) \
    asm volatile("cp.async.cg.shared.global [%0], [%1], 16;" :: "r"(dst), "l"(src))
#define CP_COMMIT() asm volatile("cp.async.commit_group;" ::: "memory")
#define CP_WAIT1()  asm volatile("cp.async.wait_group 1;" ::: "memory")

#define LDSM4(R0, R1, R2, R3, A) \
    asm volatile("ldmatrix.sync.aligned.m8n8.x4.shared.b16 {%0,%1,%2,%3}, [%4];" \
                 : "=r"(R0), "=r"(R1), "=r"(R2), "=r"(R3) : "r"(A))

#define MMAH(D, A0, A1, A2, A3, B0, B1) \
    asm volatile("mma.sync.aligned.m16n8k16.row.col.f32.f16.f16.f32 " \
                 "{%0,%1,%2,%3},{%4,%5,%6,%7},{%8,%9},{%0,%1,%2,%3};" \
                 : "+f"((D)[0]), "+f"((D)[1]), "+f"((D)[2]), "+f"((D)[3]) \
                 : "r"(A0), "r"(A1), "r"(A2), "r"(A3), "r"(B0), "r"(B1))

// ------------------------------- MMA GEMM ----------------------------------
// C[M,N] = alpha*(A @ Bmat^T)(+bias). A:[M,K] fp16 (ld=K), Bmat:[N,K] fp16 (ld=K).
// Block 128x128, 8 warps (4m x 2n), warp tile 32x64, K-chunk 64, 3-stage cp.async.
#define BMm 128
#define BNm 128
#define BKm 64
#define LDSm 72                          // padded row length in halves (144B)
#define OPA (128 * LDSm * 2)             // 18432 B
#define STGB (2 * OPA)                   // 36864 B
#define NSTAGE 3
#define SMEM_BYTES (NSTAGE * STGB)       // 110592

// EPI: 0 fp32 out, 1 fp16 out.  BIASMODE: 0 none, 1 per-col, 2 per-row.
template<int EPI, int BIASMODE>
__global__ __launch_bounds__(256, 2)
void mma_gemm(const __half* __restrict__ A, const __half* __restrict__ B,
              const float* __restrict__ bias,
              float* __restrict__ Cf, __half* __restrict__ Ch,
              int K, int ldc,
              long long sA, long long sB, long long sC, long long sBias, float alpha)
{
    extern __shared__ char smem[];
    const uint32_t sbase = smem_u32(smem);
    const int tid  = threadIdx.x;
    const int wid  = tid >> 5;
    const int lane = tid & 31;
    const int wy = wid >> 1;            // 0..3  (m, 32 rows each)
    const int wx = wid & 1;             // 0..1  (n, 64 cols each)
    const int m0 = blockIdx.y * BMm;
    const int n0 = blockIdx.x * BNm;
    A += (long long)blockIdx.z * sA;
    B += (long long)blockIdx.z * sB;
    if (BIASMODE) bias += (long long)blockIdx.z * sBias;

    float acc[2][8][4];
#pragma unroll
    for (int i = 0; i < 2; i++)
#pragma unroll
        for (int j = 0; j < 8; j++)
#pragma unroll
            for (int q = 0; q < 4; q++) acc[i][j][q] = 0.0f;

    const int nch = K / BKm;

    // hoisted per-thread gmem pointers and smem store offset for cp.async
    const int rA = tid >> 3, cA = tid & 7;
    const __half* gA = A + (long long)(m0 + rA) * K + cA * 8;
    const __half* gB = B + (long long)(n0 + rA) * K + cA * 8;
    const uint32_t soff = (uint32_t)(rA * LDSm + cA * 8) * 2;
    const long long gstep = (long long)32 * K;                 // 32 rows

    // full-stage load (prologue only)
    auto load_stage = [&](uint32_t sb, int k0) {
#pragma unroll
        for (int t = 0; t < 4; t++)
            CP16(sb + soff + t * (32 * LDSm * 2), gA + t * gstep + k0);
#pragma unroll
        for (int t = 0; t < 4; t++)
            CP16(sb + OPA + soff + t * (32 * LDSm * 2), gB + t * gstep + k0);
    };

    // 1/8th of a stage load; p in [0,8)
    auto load_part = [&](uint32_t sb, int k0, int p) {
        if (p < 4)
            CP16(sb + soff + p * (32 * LDSm * 2), gA + p * gstep + k0);
        else
            CP16(sb + OPA + soff + (p - 4) * (32 * LDSm * 2), gB + (p - 4) * gstep + k0);
    };

    load_stage(sbase, 0);           CP_COMMIT();
    load_stage(sbase + STGB, BKm);  CP_COMMIT();

    // ldmatrix lane base addresses (smem-stage-relative)
    const int arow = (lane & 7) + ((lane >> 3) & 1) * 8;   // 0..15
    const int acol = (lane >> 4) * 8;                      // 0 / 8
    const int brow = (lane & 7) + (lane >> 4) * 8;
    const int bcol = ((lane >> 3) & 1) * 8;
    const uint32_t baseA = (uint32_t)((32 * wy + arow) * LDSm + acol) * 2;
    const uint32_t baseB = (uint32_t)((64 * wx + brow) * LDSm + bcol) * 2 + OPA;

    uint32_t af[2][2][4];      // A fragments, double buffered over ks
    uint32_t bf[2][4][2];      // B fragments, rolling buffer per half-ks (4 j each)

    auto ldA = [&](int buf, uint32_t sb, int ks) {
#pragma unroll
        for (int i = 0; i < 2; i++) {
            uint32_t aoff = sb + baseA + (uint32_t)(16 * i * LDSm + ks * 16) * 2;
            LDSM4(af[buf][i][0], af[buf][i][1], af[buf][i][2], af[buf][i][3], aoff);
        }
    };
    auto ldB = [&](int buf, uint32_t sb, int ks, int jh) {
#pragma unroll
        for (int jpp = 0; jpp < 2; jpp++) {
            uint32_t boff = sb + baseB
                          + (uint32_t)(16 * (2 * jh + jpp) * LDSm + ks * 16) * 2;
            LDSM4(bf[buf][2*jpp][0], bf[buf][2*jpp][1], bf[buf][2*jpp+1][0], bf[buf][2*jpp+1][1],
                  boff);
        }
    };

    uint32_t sb_cur = sbase;                  // stage for chunk c
    uint32_t sb_pf  = sbase + 2 * STGB;       // stage for chunk c+2
    int k_pf = 2 * BKm;                       // k0 for chunk c+2

    for (int c = 0; c < nch; c++) {
        CP_WAIT1();
        __syncthreads();
        const uint32_t sb = sb_cur;
        const bool pf = (c + 2 < nch);
        const uint32_t s2 = sb_pf;
        const int k2 = k_pf;

        ldA(0, sb, 0);
        ldB(0, sb, 0, 0);
#pragma unroll
        for (int idx = 0; idx < 8; idx++) {          // ks = idx>>1, jh = idx&1
            const int ks = idx >> 1, jh = idx & 1;
            if (idx < 7) ldB((idx + 1) & 1, sb, (idx + 1) >> 1, (idx + 1) & 1);
            if (jh == 0 && ks < 3) ldA((ks + 1) & 1, sb, ks + 1);
            if (pf) load_part(s2, k2, idx);
            const int ab = ks & 1, bb = idx & 1;
#pragma unroll
            for (int i = 0; i < 2; i++)
#pragma unroll
                for (int jj = 0; jj < 4; jj++)
                    MMAH(acc[i][jh * 4 + jj],
                         af[ab][i][0], af[ab][i][1], af[ab][i][2], af[ab][i][3],
                         bf[bb][jj][0], bf[bb][jj][1]);
        }
        CP_COMMIT();
        // rotate stage pointers (no modulo)
        sb_cur += STGB; if (sb_cur == sbase + NSTAGE * STGB) sb_cur = sbase;
        sb_pf  += STGB; if (sb_pf  == sbase + NSTAGE * STGB) sb_pf  = sbase;
        k_pf   += BKm;
    }

    // ------------------------------ epilogue --------------------------------
    const int g  = lane >> 2;
    const int t4 = lane & 3;
    const long long cb = (long long)blockIdx.z * sC;
#pragma unroll
    for (int i = 0; i < 2; i++) {
#pragma unroll
        for (int j = 0; j < 8; j++) {
            int mrow = m0 + 32 * wy + 16 * i + g;
            int ncol = n0 + 64 * wx + 8 * j + 2 * t4;
            float v00 = acc[i][j][0] * alpha, v01 = acc[i][j][1] * alpha;
            float v10 = acc[i][j][2] * alpha, v11 = acc[i][j][3] * alpha;
            long long o0 = cb + (long long)mrow * ldc + ncol;
            long long o1 = cb + (long long)(mrow + 8) * ldc + ncol;
            if (BIASMODE == 1) {
                float b0 = bias[ncol], b1 = bias[ncol + 1];
                v00 += b0; v01 += b1; v10 += b0; v11 += b1;
            } else if (BIASMODE == 2) {
                float br0 = bias[mrow], br1 = bias[mrow + 8];
                v00 += br0; v01 += br0; v10 += br1; v11 += br1;
            }
            if (EPI == 0) {
                *(float2*)(Cf + o0) = make_float2(v00, v01);
                *(float2*)(Cf + o1) = make_float2(v10, v11);
            } else {
                *(__half2*)(Ch + o0) = __floats2half2_rn(v00, v01);
                *(__half2*)(Ch + o1) = __floats2half2_rn(v10, v11);
            }
        }
    }
}

// --------------------------- aux kernels ------------------------------------
// fp32 -> fp16 AND copy x into out[:, 0:D] (concat first half, off critical path)
__global__ void cvt_x(const float* __restrict__ in, __half* __restrict__ out16,
                      float* __restrict__ outx)
{
    long long i = ((long long)blockIdx.x * blockDim.x + threadIdx.x) * 4;
    float4 v = *(const float4*)(in + i);
    *(__half2*)(out16 + i)     = __floats2half2_rn(v.x, v.y);
    *(__half2*)(out16 + i + 2) = __floats2half2_rn(v.z, v.w);
    long long row = i >> 10;              // / Dd
    long long col = i & (Dd - 1);
    *(float4*)(outx + row * (2 * Dd) + col) = v;
}

__global__ void copy_bias(const float* __restrict__ b0, const float* __restrict__ b1,
                          float* __restrict__ dst)
{
    int z = blockIdx.x;
    const float* s = (z == 0) ? b0 : b1;
    dst[z * Dd + threadIdx.x] = s[threadIdx.x];
}

// Wt[n,k] = W[k,n] fp16 ; z selects which W
__global__ void transW(const float* __restrict__ W0, const float* __restrict__ W1,
                       const float* __restrict__ W2, __half* __restrict__ out)
{
    __shared__ float t[32][33];
    const float* W = (blockIdx.z == 0) ? W0 : (blockIdx.z == 1) ? W1 : W2;
    __half* o = out + (size_t)blockIdx.z * Dd * Dd;
    int bx = blockIdx.x * 32, by = blockIdx.y * 32;
    int tx = threadIdx.x, ty = threadIdx.y;
#pragma unroll
    for (int r = 0; r < 4; r++)
        t[ty + 8 * r][tx] = W[(long long)(by + ty + 8 * r) * Dd + bx + tx];
    __syncthreads();
#pragma unroll
    for (int r = 0; r < 4; r++)
        o[(long long)(bx + ty + 8 * r) * Dd + by + tx] = __float2half_rn(t[tx][ty + 8 * r]);
}

// single-read row softmax: values held in registers; writes fp32 + fp16
__global__ void softmax_split(float* __restrict__ W, __half* __restrict__ wh)
{
    long long row = blockIdx.x;
    float* p = W + row * (long long)Nn;
    __half* ph = wh + row * (long long)Nn;
    __shared__ float red[8];
    const int tid = threadIdx.x;
    const int lane = tid & 31, warp = tid >> 5;

    float e[8];
    {
        float4 v0 = *(const float4*)(p + tid * 8);
        float4 v1 = *(const float4*)(p + tid * 8 + 4);
        e[0]=v0.x; e[1]=v0.y; e[2]=v0.z; e[3]=v0.w;
        e[4]=v1.x; e[5]=v1.y; e[6]=v1.z; e[7]=v1.w;
    }
    float mx = e[0];
#pragma unroll
    for (int i = 1; i < 8; i++) mx = fmaxf(mx, e[i]);
#pragma unroll
    for (int s = 16; s > 0; s >>= 1)
        mx = fmaxf(mx, __shfl_xor_sync(0xffffffffu, mx, s));
    if (lane == 0) red[warp] = mx;
    __syncthreads();
    mx = red[0];
#pragma unroll
    for (int w = 1; w < 8; w++) mx = fmaxf(mx, red[w]);
    __syncthreads();

    float sum = 0.0f;
#pragma unroll
    for (int i = 0; i < 8; i++) { e[i] = expf(e[i] - mx); sum += e[i]; }
#pragma unroll
    for (int s = 16; s > 0; s >>= 1)
        sum += __shfl_xor_sync(0xffffffffu, sum, s);
    if (lane == 0) red[warp] = sum;
    __syncthreads();
    sum = red[0];
#pragma unroll
    for (int w = 1; w < 8; w++) sum += red[w];
    float inv = 1.0f / sum;

    float4 o0, o1;
    o0.x = e[0]*inv; o0.y = e[1]*inv; o0.z = e[2]*inv; o0.w = e[3]*inv;
    o1.x = e[4]*inv; o1.y = e[5]*inv; o1.z = e[6]*inv; o1.w = e[7]*inv;
    *(float4*)(p + tid * 8)     = o0;
    *(float4*)(p + tid * 8 + 4) = o1;
    *(__half2*)(ph + tid * 8)     = __floats2half2_rn(o0.x, o0.y);
    *(__half2*)(ph + tid * 8 + 2) = __floats2half2_rn(o0.z, o0.w);
    *(__half2*)(ph + tid * 8 + 4) = __floats2half2_rn(o1.x, o1.y);
    *(__half2*)(ph + tid * 8 + 6) = __floats2half2_rn(o1.z, o1.w);
}

// residual + layernorm (warp-shuffle reductions); writes only out[:, D:2D]
__global__ void ln_concat(const float* __restrict__ x, const float* __restrict__ att,
                          const float* __restrict__ gamma, const float* __restrict__ beta,
                          float* __restrict__ out)
{
    long long row = blockIdx.x;
    const float* xr = x + row * Dd;
    const float* ar = att + row * Dd;
    float* o = out + row * (2 * Dd);
    __shared__ float red[8];
    const int tid = threadIdx.x;
    const int lane = tid & 31, warp = tid >> 5;

    float h[4], s = 0.0f;
#pragma unroll
    for (int i = 0; i < 4; i++) { int c = tid + i * 256; h[i] = xr[c] + ar[c]; s += h[i]; }
#pragma unroll
    for (int st = 16; st > 0; st >>= 1)
        s += __shfl_xor_sync(0xffffffffu, s, st);
    if (lane == 0) red[warp] = s;
    __syncthreads();
    s = red[0];
#pragma unroll
    for (int w = 1; w < 8; w++) s += red[w];
    float mu = s * (1.0f / Dd);
    __syncthreads();

    float v = 0.0f;
#pragma unroll
    for (int i = 0; i < 4; i++) { float d = h[i] - mu; v += d * d; }
#pragma unroll
    for (int st = 16; st > 0; st >>= 1)
        v += __shfl_xor_sync(0xffffffffu, v, st);
    if (lane == 0) red[warp] = v;
    __syncthreads();
    v = red[0];
#pragma unroll
    for (int w = 1; w < 8; w++) v += red[w];
    float rstd = rsqrtf(v * (1.0f / Dd) + 1e-5f);

#pragma unroll
    for (int i = 0; i < 4; i++) {
        int c = tid + i * 256;
        o[Dd + c] = (h[i] - mu) * rstd * gamma[c] + beta[c];
    }
}

// ------------------------------- launcher -----------------------------------
extern "C" void kernel_launch(void* const* d_in, const int* in_sizes, int n_in,
                              void* d_out, int out_size)
{
    const float* x     = (const float*)d_in[0];
    const float* Wk    = (const float*)d_in[1];
    const float* bk    = (const float*)d_in[2];
    const float* Wq    = (const float*)d_in[3];
    const float* bq    = (const float*)d_in[4];
    const float* Wv    = (const float*)d_in[5];
    const float* bv    = (const float*)d_in[6];
    const float* gamma = (const float*)d_in[7];
    const float* beta  = (const float*)d_in[8];

    float* out = (float*)d_out;
    float* att = out + (long long)MT * 2 * Dd;
    float* wgt = att + (long long)MT * Dd;

    __half *x16, *W16, *QK, *Vt, *w16;
    float* bqk;
    cudaGetSymbolAddress((void**)&x16, g_x16);
    cudaGetSymbolAddress((void**)&W16, g_W16);
    cudaGetSymbolAddress((void**)&bqk, g_b);
    cudaGetSymbolAddress((void**)&QK,  g_QK);
    cudaGetSymbolAddress((void**)&Vt,  g_Vt);
    cudaGetSymbolAddress((void**)&w16, g_w16);

    cudaFuncSetAttribute(mma_gemm<0, 0>, cudaFuncAttributeMaxDynamicSharedMemorySize, SMEM_BYTES);
    cudaFuncSetAttribute(mma_gemm<1, 1>, cudaFuncAttributeMaxDynamicSharedMemorySize, SMEM_BYTES);
    cudaFuncSetAttribute(mma_gemm<1, 2>, cudaFuncAttributeMaxDynamicSharedMemorySize, SMEM_BYTES);

    // 1) precision conversions (+ concat x half)
    cvt_x<<<MT * Dd / 4096, 1024>>>(x, x16, out);
    copy_bias<<<2, Dd>>>(bq, bk, bqk);
    {
        dim3 g(Dd / 32, Dd / 32, 3), b(32, 8);
        transW<<<g, b>>>(Wq, Wk, Wv, W16);
    }

    // 2) fused Q,K projection: z in {Q,K}
    {
        dim3 g(Dd / BNm, MT / BMm, 2), b(256);
        mma_gemm<1, 1><<<g, b, SMEM_BYTES>>>(x16, W16, bqk, nullptr, QK,
                                             Dd, Dd,
                                             0, (long long)Dd * Dd, (long long)MT * Dd,
                                             Dd, 1.0f);
    }

    // 3) Vt[b][d,n] = Wv^T @ x_b^T + bv (bias per row) -> fp16, per batch
    {
        dim3 g(Nn / BNm, Dd / BMm, Bb), b(256);
        mma_gemm<1, 2><<<g, b, SMEM_BYTES>>>(W16 + (size_t)2 * Dd * Dd, x16, bv,
                                             nullptr, Vt,
                                             Dd, Nn,
                                             0, (long long)Nn * Dd, (long long)Dd * Nn,
                                             0, 1.0f);
    }

    // 4) scores = Q @ K^T / 32 -> wgt (fp32)
    {
        dim3 g(Nn / BNm, Nn / BMm, Bb), b(256);
        mma_gemm<0, 0><<<g, b, SMEM_BYTES>>>(QK, QK + (size_t)MT * Dd, nullptr,
                                             wgt, nullptr,
                                             Dd, Nn,
                                             (long long)Nn * Dd, (long long)Nn * Dd,
                                             (long long)Nn * Nn, 0, 1.0f / 32.0f);
    }

    // 5) softmax rows in place + fp16 copy (single gmem read)
    softmax_split<<<Bb * Nn, 256>>>(wgt, w16);

    // 6) att = weight @ V -> att (fp32)
    {
        dim3 g(Dd / BNm, Nn / BMm, Bb), b(256);
        mma_gemm<0, 0><<<g, b, SMEM_BYTES>>>(w16, Vt, nullptr, att, nullptr,
                                             Nn, Dd,
                                             (long long)Nn * Nn, (long long)Nn * Dd,
                                             (long long)Nn * Dd, 0, 1.0f);
    }

    // 7) out[:, D:2D] = LN(x + att)
    ln_concat<<<Bb * Nn, 256>>>(x, att, gamma, beta, out);
}

// round 14
// speedup vs baseline: 1.0810x; 1.0004x over previous
#include <cuda_runtime.h>
#include <cuda_fp16.h>
#include <math.h>
#include <stdint.h>

// ---------------------------------------------------------------------------
// attention_83932250898666 : B=4, N=2048, D=1024
// d_out layout (float32):
//   [0, 16777216)        out   = concat(x, LN(x+att))   [B,N,2D]
//   [16777216, 25165824) att_score                      [B,N,D]
//   [25165824, 41943040) weight = softmax(QK^T/32)      [B,N,N]
// GEMMs: single-pass fp16 mma.sync (HMMA), fp32 accumulate.
// Round 14: scores emitted fp16 (halved scores->softmax traffic);
//           float4 ln_concat. GEMM kernel identical to round 13.
// ---------------------------------------------------------------------------

#define Bb 4
#define Nn 2048
#define Dd 1024
#define MT (Bb*Nn)   // 8192

// ------------------------- device scratch (no allocs) ----------------------
__device__ __half g_x16[(size_t)MT * Dd];
__device__ __half g_W16[(size_t)3 * Dd * Dd];      // [z][n][k] transposed weights
__device__ float  g_b[2 * Dd];                     // biases q,k
__device__ __half g_QK[(size_t)2 * MT * Dd];       // Q | K
__device__ __half g_Vt[(size_t)MT * Dd];           // per-batch V^T [b][d][n]
__device__ __half g_s16[(size_t)Bb * Nn * Nn];     // raw scores fp16
__device__ __half g_w16[(size_t)Bb * Nn * Nn];     // softmax weights fp16

// ------------------------------ PTX helpers --------------------------------
__device__ __forceinline__ uint32_t smem_u32(const void* p) {
    uint32_t a;
    asm("{ .reg .u64 t; cvta.to.shared.u64 t, %1; cvt.u32.u64 %0, t; }" : "=r"(a) : "l"(p));
    return a;
}

#define CP16(dst, src) \
    asm volatile("cp.async.cg.shared.global [%0], [%1], 16;" :: "r"(dst), "l"(src))
#define CP_COMMIT() asm volatile("cp.async.commit_group;" ::: "memory")
#define CP_WAIT1()  asm volatile("cp.async.wait_group 1;" ::: "memory")

#define LDSM4(R0, R1, R2, R3, A) \
    asm volatile("ldmatrix.sync.aligned.m8n8.x4.shared.b16 {%0,%1,%2,%3}, [%4];" \
                 : "=r"(R0), "=r"(R1), "=r"(R2), "=r"(R3) : "r"(A))

#define MMAH(D, A0, A1, A2, A3, B0, B1) \
    asm volatile("mma.sync.aligned.m16n8k16.row.col.f32.f16.f16.f32 " \
                 "{%0,%1,%2,%3},{%4,%5,%6,%7},{%8,%9},{%0,%1,%2,%3};" \
                 : "+f"((D)[0]), "+f"((D)[1]), "+f"((D)[2]), "+f"((D)[3]) \
                 : "r"(A0), "r"(A1), "r"(A2), "r"(A3), "r"(B0), "r"(B1))

// ------------------------------- MMA GEMM ----------------------------------
// C[M,N] = alpha*(A @ Bmat^T)(+bias). A:[M,K] fp16 (ld=K), Bmat:[N,K] fp16 (ld=K).
// Block 128x128, 8 warps (4m x 2n), warp tile 32x64, K-chunk 64, 3-stage cp.async.
#define BMm 128
#define BNm 128
#define BKm 64
#define LDSm 72                          // padded row length in halves (144B)
#define OPA (128 * LDSm * 2)             // 18432 B
#define STGB (2 * OPA)                   // 36864 B
#define NSTAGE 3
#define SMEM_BYTES (NSTAGE * STGB)       // 110592

// EPI: 0 fp32 out, 1 fp16 out.  BIASMODE: 0 none, 1 per-col, 2 per-row.
template<int EPI, int BIASMODE>
__global__ __launch_bounds__(256, 2)
void mma_gemm(const __half* __restrict__ A, const __half* __restrict__ B,
              const float* __restrict__ bias,
              float* __restrict__ Cf, __half* __restrict__ Ch,
              int K, int ldc,
              long long sA, long long sB, long long sC, long long sBias, float alpha)
{
    extern __shared__ char smem[];
    const uint32_t sbase = smem_u32(smem);
    const int tid  = threadIdx.x;
    const int wid  = tid >> 5;
    const int lane = tid & 31;
    const int wy = wid >> 1;            // 0..3  (m, 32 rows each)
    const int wx = wid & 1;             // 0..1  (n, 64 cols each)
    const int m0 = blockIdx.y * BMm;
    const int n0 = blockIdx.x * BNm;
    A += (long long)blockIdx.z * sA;
    B += (long long)blockIdx.z * sB;
    if (BIASMODE) bias += (long long)blockIdx.z * sBias;

    float acc[2][8][4];
#pragma unroll
    for (int i = 0; i < 2; i++)
#pragma unroll
        for (int j = 0; j < 8; j++)
#pragma unroll
            for (int q = 0; q < 4; q++) acc[i][j][q] = 0.0f;

    const int nch = K / BKm;

    // hoisted per-thread gmem pointers and smem store offset for cp.async
    const int rA = tid >> 3, cA = tid & 7;
    const __half* gA = A + (long long)(m0 + rA) * K + cA * 8;
    const __half* gB = B + (long long)(n0 + rA) * K + cA * 8;
    const uint32_t soff = (uint32_t)(rA * LDSm + cA * 8) * 2;
    const long long gstep = (long long)32 * K;                 // 32 rows

    // full-stage load (prologue only)
    auto load_stage = [&](uint32_t sb, int k0) {
#pragma unroll
        for (int t = 0; t < 4; t++)
            CP16(sb + soff + t * (32 * LDSm * 2), gA + t * gstep + k0);
#pragma unroll
        for (int t = 0; t < 4; t++)
            CP16(sb + OPA + soff + t * (32 * LDSm * 2), gB + t * gstep + k0);
    };

    // 1/8th of a stage load; p in [0,8)
    auto load_part = [&](uint32_t sb, int k0, int p) {
        if (p < 4)
            CP16(sb + soff + p * (32 * LDSm * 2), gA + p * gstep + k0);
        else
            CP16(sb + OPA + soff + (p - 4) * (32 * LDSm * 2), gB + (p - 4) * gstep + k0);
    };

    load_stage(sbase, 0);           CP_COMMIT();
    load_stage(sbase + STGB, BKm);  CP_COMMIT();

    // ldmatrix lane base addresses (smem-stage-relative)
    const int arow = (lane & 7) + ((lane >> 3) & 1) * 8;   // 0..15
    const int acol = (lane >> 4) * 8;                      // 0 / 8
    const int brow = (lane & 7) + (lane >> 4) * 8;
    const int bcol = ((lane >> 3) & 1) * 8;
    const uint32_t baseA = (uint32_t)((32 * wy + arow) * LDSm + acol) * 2;
    const uint32_t baseB = (uint32_t)((64 * wx + brow) * LDSm + bcol) * 2 + OPA;

    uint32_t af[2][2][4];      // A fragments, double buffered over ks
    uint32_t bf[2][4][2];      // B fragments, rolling buffer per half-ks (4 j each)

    auto ldA = [&](int buf, uint32_t sb, int ks) {
#pragma unroll
        for (int i = 0; i < 2; i++) {
            uint32_t aoff = sb + baseA + (uint32_t)(16 * i * LDSm + ks * 16) * 2;
            LDSM4(af[buf][i][0], af[buf][i][1], af[buf][i][2], af[buf][i][3], aoff);
        }
    };
    auto ldB = [&](int buf, uint32_t sb, int ks, int jh) {
#pragma unroll
        for (int jpp = 0; jpp < 2; jpp++) {
            uint32_t boff = sb + baseB
                          + (uint32_t)(16 * (2 * jh + jpp) * LDSm + ks * 16) * 2;
            LDSM4(bf[buf][2*jpp][0], bf[buf][2*jpp][1], bf[buf][2*jpp+1][0], bf[buf][2*jpp+1][1],
                  boff);
        }
    };

    uint32_t sb_cur = sbase;                  // stage for chunk c
    uint32_t sb_pf  = sbase + 2 * STGB;       // stage for chunk c+2
    int k_pf = 2 * BKm;                       // k0 for chunk c+2

    for (int c = 0; c < nch; c++) {
        CP_WAIT1();
        __syncthreads();
        const uint32_t sb = sb_cur;
        const bool pf = (c + 2 < nch);
        const uint32_t s2 = sb_pf;
        const int k2 = k_pf;

        ldA(0, sb, 0);
        ldB(0, sb, 0, 0);
#pragma unroll
        for (int idx = 0; idx < 8; idx++) {          // ks = idx>>1, jh = idx&1
            const int ks = idx >> 1, jh = idx & 1;
            if (idx < 7) ldB((idx + 1) & 1, sb, (idx + 1) >> 1, (idx + 1) & 1);
            if (jh == 0 && ks < 3) ldA((ks + 1) & 1, sb, ks + 1);
            if (pf) load_part(s2, k2, idx);
            const int ab = ks & 1, bb = idx & 1;
#pragma unroll
            for (int i = 0; i < 2; i++)
#pragma unroll
                for (int jj = 0; jj < 4; jj++)
                    MMAH(acc[i][jh * 4 + jj],
                         af[ab][i][0], af[ab][i][1], af[ab][i][2], af[ab][i][3],
                         bf[bb][jj][0], bf[bb][jj][1]);
        }
        CP_COMMIT();
        // rotate stage pointers (no modulo)
        sb_cur += STGB; if (sb_cur == sbase + NSTAGE * STGB) sb_cur = sbase;
        sb_pf  += STGB; if (sb_pf  == sbase + NSTAGE * STGB) sb_pf  = sbase;
        k_pf   += BKm;
    }

    // ------------------------------ epilogue --------------------------------
    const int g  = lane >> 2;
    const int t4 = lane & 3;
    const long long cb = (long long)blockIdx.z * sC;
#pragma unroll
    for (int i = 0; i < 2; i++) {
#pragma unroll
        for (int j = 0; j < 8; j++) {
            int mrow = m0 + 32 * wy + 16 * i + g;
            int ncol = n0 + 64 * wx + 8 * j + 2 * t4;
            float v00 = acc[i][j][0] * alpha, v01 = acc[i][j][1] * alpha;
            float v10 = acc[i][j][2] * alpha, v11 = acc[i][j][3] * alpha;
            long long o0 = cb + (long long)mrow * ldc + ncol;
            long long o1 = cb + (long long)(mrow + 8) * ldc + ncol;
            if (BIASMODE == 1) {
                float b0 = bias[ncol], b1 = bias[ncol + 1];
                v00 += b0; v01 += b1; v10 += b0; v11 += b1;
            } else if (BIASMODE == 2) {
                float br0 = bias[mrow], br1 = bias[mrow + 8];
                v00 += br0; v01 += br0; v10 += br1; v11 += br1;
            }
            if (EPI == 0) {
                *(float2*)(Cf + o0) = make_float2(v00, v01);
                *(float2*)(Cf + o1) = make_float2(v10, v11);
            } else {
                *(__half2*)(Ch + o0) = __floats2half2_rn(v00, v01);
                *(__half2*)(Ch + o1) = __floats2half2_rn(v10, v11);
            }
        }
    }
}

// --------------------------- aux kernels ------------------------------------
// fp32 -> fp16 AND copy x into out[:, 0:D] (concat first half, off critical path)
__global__ void cvt_x(const float* __restrict__ in, __half* __restrict__ out16,
                      float* __restrict__ outx)
{
    long long i = ((long long)blockIdx.x * blockDim.x + threadIdx.x) * 4;
    float4 v = *(const float4*)(in + i);
    *(__half2*)(out16 + i)     = __floats2half2_rn(v.x, v.y);
    *(__half2*)(out16 + i + 2) = __floats2half2_rn(v.z, v.w);
    long long row = i >> 10;              // / Dd
    long long col = i & (Dd - 1);
    *(float4*)(outx + row * (2 * Dd) + col) = v;
}

__global__ void copy_bias(const float* __restrict__ b0, const float* __restrict__ b1,
                          float* __restrict__ dst)
{
    int z = blockIdx.x;
    const float* s = (z == 0) ? b0 : b1;
    dst[z * Dd + threadIdx.x] = s[threadIdx.x];
}

// Wt[n,k] = W[k,n] fp16 ; z selects which W
__global__ void transW(const float* __restrict__ W0, const float* __restrict__ W1,
                       const float* __restrict__ W2, __half* __restrict__ out)
{
    __shared__ float t[32][33];
    const float* W = (blockIdx.z == 0) ? W0 : (blockIdx.z == 1) ? W1 : W2;
    __half* o = out + (size_t)blockIdx.z * Dd * Dd;
    int bx = blockIdx.x * 32, by = blockIdx.y * 32;
    int tx = threadIdx.x, ty = threadIdx.y;
#pragma unroll
    for (int r = 0; r < 4; r++)
        t[ty + 8 * r][tx] = W[(long long)(by + ty + 8 * r) * Dd + bx + tx];
    __syncthreads();
#pragma unroll
    for (int r = 0; r < 4; r++)
        o[(long long)(bx + ty + 8 * r) * Dd + by + tx] = __float2half_rn(t[tx][ty + 8 * r]);
}

// softmax: reads raw fp16 scores, computes fp32, writes fp32 weight + fp16 copy
__global__ void softmax_split(const __half* __restrict__ S, float* __restrict__ W,
                              __half* __restrict__ wh)
{
    long long row = blockIdx.x;
    const __half* ps = S + row * (long long)Nn;
    float* p = W + row * (long long)Nn;
    __half* ph = wh + row * (long long)Nn;
    __shared__ float red[8];
    const int tid = threadIdx.x;
    const int lane = tid & 31, warp = tid >> 5;

    float e[8];
    {
        uint4 raw = *(const uint4*)(ps + tid * 8);     // 8 halves
        __half2 h0 = *(__half2*)&raw.x;
        __half2 h1 = *(__half2*)&raw.y;
        __half2 h2 = *(__half2*)&raw.z;
        __half2 h3 = *(__half2*)&raw.w;
        float2 f0 = __half22float2(h0), f1 = __half22float2(h1);
        float2 f2 = __half22float2(h2), f3 = __half22float2(h3);
        e[0]=f0.x; e[1]=f0.y; e[2]=f1.x; e[3]=f1.y;
        e[4]=f2.x; e[5]=f2.y; e[6]=f3.x; e[7]=f3.y;
    }
    float mx = e[0];
#pragma unroll
    for (int i = 1; i < 8; i++) mx = fmaxf(mx, e[i]);
#pragma unroll
    for (int s = 16; s > 0; s >>= 1)
        mx = fmaxf(mx, __shfl_xor_sync(0xffffffffu, mx, s));
    if (lane == 0) red[warp] = mx;
    __syncthreads();
    mx = red[0];
#pragma unroll
    for (int w = 1; w < 8; w++) mx = fmaxf(mx, red[w]);
    __syncthreads();

    float sum = 0.0f;
#pragma unroll
    for (int i = 0; i < 8; i++) { e[i] = expf(e[i] - mx); sum += e[i]; }
#pragma unroll
    for (int s = 16; s > 0; s >>= 1)
        sum += __shfl_xor_sync(0xffffffffu, sum, s);
    if (lane == 0) red[warp] = sum;
    __syncthreads();
    sum = red[0];
#pragma unroll
    for (int w = 1; w < 8; w++) sum += red[w];
    float inv = 1.0f / sum;

    float4 o0, o1;
    o0.x = e[0]*inv; o0.y = e[1]*inv; o0.z = e[2]*inv; o0.w = e[3]*inv;
    o1.x = e[4]*inv; o1.y = e[5]*inv; o1.z = e[6]*inv; o1.w = e[7]*inv;
    *(float4*)(p + tid * 8)     = o0;
    *(float4*)(p + tid * 8 + 4) = o1;
    *(__half2*)(ph + tid * 8)     = __floats2half2_rn(o0.x, o0.y);
    *(__half2*)(ph + tid * 8 + 2) = __floats2half2_rn(o0.z, o0.w);
    *(__half2*)(ph + tid * 8 + 4) = __floats2half2_rn(o1.x, o1.y);
    *(__half2*)(ph + tid * 8 + 6) = __floats2half2_rn(o1.z, o1.w);
}

// residual + layernorm (warp-shuffle reductions, float4 I/O); writes out[:, D:2D]
__global__ void ln_concat(const float* __restrict__ x, const float* __restrict__ att,
                          const float* __restrict__ gamma, const float* __restrict__ beta,
                          float* __restrict__ out)
{
    long long row = blockIdx.x;
    const float* xr = x + row * Dd;
    const float* ar = att + row * Dd;
    float* o = out + row * (2 * Dd);
    __shared__ float red[8];
    const int tid = threadIdx.x;
    const int lane = tid & 31, warp = tid >> 5;
    const int c0 = tid * 4;

    float4 xv = *(const float4*)(xr + c0);
    float4 av = *(const float4*)(ar + c0);
    float h[4] = {xv.x + av.x, xv.y + av.y, xv.z + av.z, xv.w + av.w};
    float s = h[0] + h[1] + h[2] + h[3];
#pragma unroll
    for (int st = 16; st > 0; st >>= 1)
        s += __shfl_xor_sync(0xffffffffu, s, st);
    if (lane == 0) red[warp] = s;
    __syncthreads();
    s = red[0];
#pragma unroll
    for (int w = 1; w < 8; w++) s += red[w];
    float mu = s * (1.0f / Dd);
    __syncthreads();

    float v = 0.0f;
#pragma unroll
    for (int i = 0; i < 4; i++) { float d = h[i] - mu; v += d * d; }
#pragma unroll
    for (int st = 16; st > 0; st >>= 1)
        v += __shfl_xor_sync(0xffffffffu, v, st);
    if (lane == 0) red[warp] = v;
    __syncthreads();
    v = red[0];
#pragma unroll
    for (int w = 1; w < 8; w++) v += red[w];
    float rstd = rsqrtf(v * (1.0f / Dd) + 1e-5f);

    float4 gv = *(const float4*)(gamma + c0);
    float4 bv = *(const float4*)(beta + c0);
    float4 ov;
    ov.x = (h[0] - mu) * rstd * gv.x + bv.x;
    ov.y = (h[1] - mu) * rstd * gv.y + bv.y;
    ov.z = (h[2] - mu) * rstd * gv.z + bv.z;
    ov.w = (h[3] - mu) * rstd * gv.w + bv.w;
    *(float4*)(o + Dd + c0) = ov;
}

// ------------------------------- launcher -----------------------------------
extern "C" void kernel_launch(void* const* d_in, const int* in_sizes, int n_in,
                              void* d_out, int out_size)
{
    const float* x     = (const float*)d_in[0];
    const float* Wk    = (const float*)d_in[1];
    const float* bk    = (const float*)d_in[2];
    const float* Wq    = (const float*)d_in[3];
    const float* bq    = (const float*)d_in[4];
    const float* Wv    = (const float*)d_in[5];
    const float* bv    = (const float*)d_in[6];
    const float* gamma = (const float*)d_in[7];
    const float* beta  = (const float*)d_in[8];

    float* out = (float*)d_out;
    float* att = out + (long long)MT * 2 * Dd;
    float* wgt = att + (long long)MT * Dd;

    __half *x16, *W16, *QK, *Vt, *s16, *w16;
    float* bqk;
    cudaGetSymbolAddress((void**)&x16, g_x16);
    cudaGetSymbolAddress((void**)&W16, g_W16);
    cudaGetSymbolAddress((void**)&bqk, g_b);
    cudaGetSymbolAddress((void**)&QK,  g_QK);
    cudaGetSymbolAddress((void**)&Vt,  g_Vt);
    cudaGetSymbolAddress((void**)&s16, g_s16);
    cudaGetSymbolAddress((void**)&w16, g_w16);

    cudaFuncSetAttribute(mma_gemm<0, 0>, cudaFuncAttributeMaxDynamicSharedMemorySize, SMEM_BYTES);
    cudaFuncSetAttribute(mma_gemm<1, 0>, cudaFuncAttributeMaxDynamicSharedMemorySize, SMEM_BYTES);
    cudaFuncSetAttribute(mma_gemm<1, 1>, cudaFuncAttributeMaxDynamicSharedMemorySize, SMEM_BYTES);
    cudaFuncSetAttribute(mma_gemm<1, 2>, cudaFuncAttributeMaxDynamicSharedMemorySize, SMEM_BYTES);

    // 1) precision conversions (+ concat x half)
    cvt_x<<<MT * Dd / 4096, 1024>>>(x, x16, out);
    copy_bias<<<2, Dd>>>(bq, bk, bqk);
    {
        dim3 g(Dd / 32, Dd / 32, 3), b(32, 8);
        transW<<<g, b>>>(Wq, Wk, Wv, W16);
    }

    // 2) fused Q,K projection: z in {Q,K}
    {
        dim3 g(Dd / BNm, MT / BMm, 2), b(256);
        mma_gemm<1, 1><<<g, b, SMEM_BYTES>>>(x16, W16, bqk, nullptr, QK,
                                             Dd, Dd,
                                             0, (long long)Dd * Dd, (long long)MT * Dd,
                                             Dd, 1.0f);
    }

    // 3) Vt[b][d,n] = Wv^T @ x_b^T + bv (bias per row) -> fp16, per batch
    {
        dim3 g(Nn / BNm, Dd / BMm, Bb), b(256);
        mma_gemm<1, 2><<<g, b, SMEM_BYTES>>>(W16 + (size_t)2 * Dd * Dd, x16, bv,
                                             nullptr, Vt,
                                             Dd, Nn,
                                             0, (long long)Nn * Dd, (long long)Dd * Nn,
                                             0, 1.0f);
    }

    // 4) scores = Q @ K^T / 32 -> s16 (fp16)
    {
        dim3 g(Nn / BNm, Nn / BMm, Bb), b(256);
        mma_gemm<1, 0><<<g, b, SMEM_BYTES>>>(QK, QK + (size_t)MT * Dd, nullptr,
                                             nullptr, s16,
                                             Dd, Nn,
                                             (long long)Nn * Dd, (long long)Nn * Dd,
                                             (long long)Nn * Nn, 0, 1.0f / 32.0f);
    }

    // 5) softmax: fp16 scores -> fp32 weight output + fp16 copy
    softmax_split<<<Bb * Nn, 256>>>(s16, wgt, w16);

    // 6) att = weight @ V -> att (fp32)
    {
        dim3 g(Dd / BNm, Nn / BMm, Bb), b(256);
        mma_gemm<0, 0><<<g, b, SMEM_BYTES>>>(w16, Vt, nullptr, att, nullptr,
                                             Nn, Dd,
                                             (long long)Nn * Nn, (long long)Nn * Dd,
                                             (long long)Nn * Dd, 0, 1.0f);
    }

    // 7) out[:, D:2D] = LN(x + att)
    ln_concat<<<Bb * Nn, 256>>>(x, att, gamma, beta, out);
}

// round 15
// speedup vs baseline: 1.1305x; 1.0458x over previous
#include <cuda_runtime.h>
#include <cuda_fp16.h>
#include <math.h>
#include <stdint.h>

// ---------------------------------------------------------------------------
// attention_83932250898666 : B=4, N=2048, D=1024
// d_out layout (float32):
//   [0, 16777216)        out   = concat(x, LN(x+att))   [B,N,2D]
//   [16777216, 25165824) att_score                      [B,N,D]
//   [25165824, 41943040) weight = softmax(QK^T/32)      [B,N,N]
// GEMMs: single-pass fp16 mma.sync (HMMA), fp32 accumulate.
// Round 15: round-14 kernels verbatim + dual-stream overlap:
//           s1 runs copy_bias/transW/Vt concurrently with cvt_x/QK/scores,
//           filling QK wave tails with Vt CTAs (capture-legal fork/join).
// ---------------------------------------------------------------------------

#define Bb 4
#define Nn 2048
#define Dd 1024
#define MT (Bb*Nn)   // 8192

// ------------------------- device scratch (no allocs) ----------------------
__device__ __half g_x16[(size_t)MT * Dd];
__device__ __half g_W16[(size_t)3 * Dd * Dd];      // [z][n][k] transposed weights
__device__ float  g_b[2 * Dd];                     // biases q,k
__device__ __half g_QK[(size_t)2 * MT * Dd];       // Q | K
__device__ __half g_Vt[(size_t)MT * Dd];           // per-batch V^T [b][d][n]
__device__ __half g_s16[(size_t)Bb * Nn * Nn];     // raw scores fp16
__device__ __half g_w16[(size_t)Bb * Nn * Nn];     // softmax weights fp16

// ---------------- streams/events (created at load, before checkpoints) -----
struct SideStream {
    cudaStream_t s1;
    cudaEvent_t e0, e1, eW, eV;
    SideStream() {
        cudaStreamCreateWithFlags(&s1, cudaStreamNonBlocking);
        cudaEventCreateWithFlags(&e0, cudaEventDisableTiming);
        cudaEventCreateWithFlags(&e1, cudaEventDisableTiming);
        cudaEventCreateWithFlags(&eW, cudaEventDisableTiming);
        cudaEventCreateWithFlags(&eV, cudaEventDisableTiming);
    }
};
static SideStream g_ss;

// ------------------------------ PTX helpers --------------------------------
__device__ __forceinline__ uint32_t smem_u32(const void* p) {
    uint32_t a;
    asm("{ .reg .u64 t; cvta.to.shared.u64 t, %1; cvt.u32.u64 %0, t; }" : "=r"(a) : "l"(p));
    return a;
}

#define CP16(dst, src) \
    asm volatile("cp.async.cg.shared.global [%0], [%1], 16;" :: "r"(dst), "l"(src))
#define CP_COMMIT() asm volatile("cp.async.commit_group;" ::: "memory")
#define CP_WAIT1()  asm volatile("cp.async.wait_group 1;" ::: "memory")

#define LDSM4(R0, R1, R2, R3, A) \
    asm volatile("ldmatrix.sync.aligned.m8n8.x4.shared.b16 {%0,%1,%2,%3}, [%4];" \
                 : "=r"(R0), "=r"(R1), "=r"(R2), "=r"(R3) : "r"(A))

#define MMAH(D, A0, A1, A2, A3, B0, B1) \
    asm volatile("mma.sync.aligned.m16n8k16.row.col.f32.f16.f16.f32 " \
                 "{%0,%1,%2,%3},{%4,%5,%6,%7},{%8,%9},{%0,%1,%2,%3};" \
                 : "+f"((D)[0]), "+f"((D)[1]), "+f"((D)[2]), "+f"((D)[3]) \
                 : "r"(A0), "r"(A1), "r"(A2), "r"(A3), "r"(B0), "r"(B1))

// ------------------------------- MMA GEMM ----------------------------------
// C[M,N] = alpha*(A @ Bmat^T)(+bias). A:[M,K] fp16 (ld=K), Bmat:[N,K] fp16 (ld=K).
// Block 128x128, 8 warps (4m x 2n), warp tile 32x64, K-chunk 64, 3-stage cp.async.
#define BMm 128
#define BNm 128
#define BKm 64
#define LDSm 72                          // padded row length in halves (144B)
#define OPA (128 * LDSm * 2)             // 18432 B
#define STGB (2 * OPA)                   // 36864 B
#define NSTAGE 3
#define SMEM_BYTES (NSTAGE * STGB)       // 110592

// EPI: 0 fp32 out, 1 fp16 out.  BIASMODE: 0 none, 1 per-col, 2 per-row.
template<int EPI, int BIASMODE>
__global__ __launch_bounds__(256, 2)
void mma_gemm(const __half* __restrict__ A, const __half* __restrict__ B,
              const float* __restrict__ bias,
              float* __restrict__ Cf, __half* __restrict__ Ch,
              int K, int ldc,
              long long sA, long long sB, long long sC, long long sBias, float alpha)
{
    extern __shared__ char smem[];
    const uint32_t sbase = smem_u32(smem);
    const int tid  = threadIdx.x;
    const int wid  = tid >> 5;
    const int lane = tid & 31;
    const int wy = wid >> 1;            // 0..3  (m, 32 rows each)
    const int wx = wid & 1;             // 0..1  (n, 64 cols each)
    const int m0 = blockIdx.y * BMm;
    const int n0 = blockIdx.x * BNm;
    A += (long long)blockIdx.z * sA;
    B += (long long)blockIdx.z * sB;
    if (BIASMODE) bias += (long long)blockIdx.z * sBias;

    float acc[2][8][4];
#pragma unroll
    for (int i = 0; i < 2; i++)
#pragma unroll
        for (int j = 0; j < 8; j++)
#pragma unroll
            for (int q = 0; q < 4; q++) acc[i][j][q] = 0.0f;

    const int nch = K / BKm;

    // hoisted per-thread gmem pointers and smem store offset for cp.async
    const int rA = tid >> 3, cA = tid & 7;
    const __half* gA = A + (long long)(m0 + rA) * K + cA * 8;
    const __half* gB = B + (long long)(n0 + rA) * K + cA * 8;
    const uint32_t soff = (uint32_t)(rA * LDSm + cA * 8) * 2;
    const long long gstep = (long long)32 * K;                 // 32 rows

    // full-stage load (prologue only)
    auto load_stage = [&](uint32_t sb, int k0) {
#pragma unroll
        for (int t = 0; t < 4; t++)
            CP16(sb + soff + t * (32 * LDSm * 2), gA + t * gstep + k0);
#pragma unroll
        for (int t = 0; t < 4; t++)
            CP16(sb + OPA + soff + t * (32 * LDSm * 2), gB + t * gstep + k0);
    };

    // 1/8th of a stage load; p in [0,8)
    auto load_part = [&](uint32_t sb, int k0, int p) {
        if (p < 4)
            CP16(sb + soff + p * (32 * LDSm * 2), gA + p * gstep + k0);
        else
            CP16(sb + OPA + soff + (p - 4) * (32 * LDSm * 2), gB + (p - 4) * gstep + k0);
    };

    load_stage(sbase, 0);           CP_COMMIT();
    load_stage(sbase + STGB, BKm);  CP_COMMIT();

    // ldmatrix lane base addresses (smem-stage-relative)
    const int arow = (lane & 7) + ((lane >> 3) & 1) * 8;   // 0..15
    const int acol = (lane >> 4) * 8;                      // 0 / 8
    const int brow = (lane & 7) + (lane >> 4) * 8;
    const int bcol = ((lane >> 3) & 1) * 8;
    const uint32_t baseA = (uint32_t)((32 * wy + arow) * LDSm + acol) * 2;
    const uint32_t baseB = (uint32_t)((64 * wx + brow) * LDSm + bcol) * 2 + OPA;

    uint32_t af[2][2][4];      // A fragments, double buffered over ks
    uint32_t bf[2][4][2];      // B fragments, rolling buffer per half-ks (4 j each)

    auto ldA = [&](int buf, uint32_t sb, int ks) {
#pragma unroll
        for (int i = 0; i < 2; i++) {
            uint32_t aoff = sb + baseA + (uint32_t)(16 * i * LDSm + ks * 16) * 2;
            LDSM4(af[buf][i][0], af[buf][i][1], af[buf][i][2], af[buf][i][3], aoff);
        }
    };
    auto ldB = [&](int buf, uint32_t sb, int ks, int jh) {
#pragma unroll
        for (int jpp = 0; jpp < 2; jpp++) {
            uint32_t boff = sb + baseB
                          + (uint32_t)(16 * (2 * jh + jpp) * LDSm + ks * 16) * 2;
            LDSM4(bf[buf][2*jpp][0], bf[buf][2*jpp][1], bf[buf][2*jpp+1][0], bf[buf][2*jpp+1][1],
                  boff);
        }
    };

    uint32_t sb_cur = sbase;                  // stage for chunk c
    uint32_t sb_pf  = sbase + 2 * STGB;       // stage for chunk c+2
    int k_pf = 2 * BKm;                       // k0 for chunk c+2

    for (int c = 0; c < nch; c++) {
        CP_WAIT1();
        __syncthreads();
        const uint32_t sb = sb_cur;
        const bool pf = (c + 2 < nch);
        const uint32_t s2 = sb_pf;
        const int k2 = k_pf;

        ldA(0, sb, 0);
        ldB(0, sb, 0, 0);
#pragma unroll
        for (int idx = 0; idx < 8; idx++) {          // ks = idx>>1, jh = idx&1
            const int ks = idx >> 1, jh = idx & 1;
            if (idx < 7) ldB((idx + 1) & 1, sb, (idx + 1) >> 1, (idx + 1) & 1);
            if (jh == 0 && ks < 3) ldA((ks + 1) & 1, sb, ks + 1);
            if (pf) load_part(s2, k2, idx);
            const int ab = ks & 1, bb = idx & 1;
#pragma unroll
            for (int i = 0; i < 2; i++)
#pragma unroll
                for (int jj = 0; jj < 4; jj++)
                    MMAH(acc[i][jh * 4 + jj],
                         af[ab][i][0], af[ab][i][1], af[ab][i][2], af[ab][i][3],
                         bf[bb][jj][0], bf[bb][jj][1]);
        }
        CP_COMMIT();
        // rotate stage pointers (no modulo)
        sb_cur += STGB; if (sb_cur == sbase + NSTAGE * STGB) sb_cur = sbase;
        sb_pf  += STGB; if (sb_pf  == sbase + NSTAGE * STGB) sb_pf  = sbase;
        k_pf   += BKm;
    }

    // ------------------------------ epilogue --------------------------------
    const int g  = lane >> 2;
    const int t4 = lane & 3;
    const long long cb = (long long)blockIdx.z * sC;
#pragma unroll
    for (int i = 0; i < 2; i++) {
#pragma unroll
        for (int j = 0; j < 8; j++) {
            int mrow = m0 + 32 * wy + 16 * i + g;
            int ncol = n0 + 64 * wx + 8 * j + 2 * t4;
            float v00 = acc[i][j][0] * alpha, v01 = acc[i][j][1] * alpha;
            float v10 = acc[i][j][2] * alpha, v11 = acc[i][j][3] * alpha;
            long long o0 = cb + (long long)mrow * ldc + ncol;
            long long o1 = cb + (long long)(mrow + 8) * ldc + ncol;
            if (BIASMODE == 1) {
                float b0 = bias[ncol], b1 = bias[ncol + 1];
                v00 += b0; v01 += b1; v10 += b0; v11 += b1;
            } else if (BIASMODE == 2) {
                float br0 = bias[mrow], br1 = bias[mrow + 8];
                v00 += br0; v01 += br0; v10 += br1; v11 += br1;
            }
            if (EPI == 0) {
                *(float2*)(Cf + o0) = make_float2(v00, v01);
                *(float2*)(Cf + o1) = make_float2(v10, v11);
            } else {
                *(__half2*)(Ch + o0) = __floats2half2_rn(v00, v01);
                *(__half2*)(Ch + o1) = __floats2half2_rn(v10, v11);
            }
        }
    }
}

// --------------------------- aux kernels ------------------------------------
// fp32 -> fp16 AND copy x into out[:, 0:D] (concat first half, off critical path)
__global__ void cvt_x(const float* __restrict__ in, __half* __restrict__ out16,
                      float* __restrict__ outx)
{
    long long i = ((long long)blockIdx.x * blockDim.x + threadIdx.x) * 4;
    float4 v = *(const float4*)(in + i);
    *(__half2*)(out16 + i)     = __floats2half2_rn(v.x, v.y);
    *(__half2*)(out16 + i + 2) = __floats2half2_rn(v.z, v.w);
    long long row = i >> 10;              // / Dd
    long long col = i & (Dd - 1);
    *(float4*)(outx + row * (2 * Dd) + col) = v;
}

__global__ void copy_bias(const float* __restrict__ b0, const float* __restrict__ b1,
                          float* __restrict__ dst)
{
    int z = blockIdx.x;
    const float* s = (z == 0) ? b0 : b1;
    dst[z * Dd + threadIdx.x] = s[threadIdx.x];
}

// Wt[n,k] = W[k,n] fp16 ; z selects which W
__global__ void transW(const float* __restrict__ W0, const float* __restrict__ W1,
                       const float* __restrict__ W2, __half* __restrict__ out)
{
    __shared__ float t[32][33];
    const float* W = (blockIdx.z == 0) ? W0 : (blockIdx.z == 1) ? W1 : W2;
    __half* o = out + (size_t)blockIdx.z * Dd * Dd;
    int bx = blockIdx.x * 32, by = blockIdx.y * 32;
    int tx = threadIdx.x, ty = threadIdx.y;
#pragma unroll
    for (int r = 0; r < 4; r++)
        t[ty + 8 * r][tx] = W[(long long)(by + ty + 8 * r) * Dd + bx + tx];
    __syncthreads();
#pragma unroll
    for (int r = 0; r < 4; r++)
        o[(long long)(bx + ty + 8 * r) * Dd + by + tx] = __float2half_rn(t[tx][ty + 8 * r]);
}

// softmax: reads raw fp16 scores, computes fp32, writes fp32 weight + fp16 copy
__global__ void softmax_split(const __half* __restrict__ S, float* __restrict__ W,
                              __half* __restrict__ wh)
{
    long long row = blockIdx.x;
    const __half* ps = S + row * (long long)Nn;
    float* p = W + row * (long long)Nn;
    __half* ph = wh + row * (long long)Nn;
    __shared__ float red[8];
    const int tid = threadIdx.x;
    const int lane = tid & 31, warp = tid >> 5;

    float e[8];
    {
        uint4 raw = *(const uint4*)(ps + tid * 8);     // 8 halves
        __half2 h0 = *(__half2*)&raw.x;
        __half2 h1 = *(__half2*)&raw.y;
        __half2 h2 = *(__half2*)&raw.z;
        __half2 h3 = *(__half2*)&raw.w;
        float2 f0 = __half22float2(h0), f1 = __half22float2(h1);
        float2 f2 = __half22float2(h2), f3 = __half22float2(h3);
        e[0]=f0.x; e[1]=f0.y; e[2]=f1.x; e[3]=f1.y;
        e[4]=f2.x; e[5]=f2.y; e[6]=f3.x; e[7]=f3.y;
    }
    float mx = e[0];
#pragma unroll
    for (int i = 1; i < 8; i++) mx = fmaxf(mx, e[i]);
#pragma unroll
    for (int s = 16; s > 0; s >>= 1)
        mx = fmaxf(mx, __shfl_xor_sync(0xffffffffu, mx, s));
    if (lane == 0) red[warp] = mx;
    __syncthreads();
    mx = red[0];
#pragma unroll
    for (int w = 1; w < 8; w++) mx = fmaxf(mx, red[w]);
    __syncthreads();

    float sum = 0.0f;
#pragma unroll
    for (int i = 0; i < 8; i++) { e[i] = expf(e[i] - mx); sum += e[i]; }
#pragma unroll
    for (int s = 16; s > 0; s >>= 1)
        sum += __shfl_xor_sync(0xffffffffu, sum, s);
    if (lane == 0) red[warp] = sum;
    __syncthreads();
    sum = red[0];
#pragma unroll
    for (int w = 1; w < 8; w++) sum += red[w];
    float inv = 1.0f / sum;

    float4 o0, o1;
    o0.x = e[0]*inv; o0.y = e[1]*inv; o0.z = e[2]*inv; o0.w = e[3]*inv;
    o1.x = e[4]*inv; o1.y = e[5]*inv; o1.z = e[6]*inv; o1.w = e[7]*inv;
    *(float4*)(p + tid * 8)     = o0;
    *(float4*)(p + tid * 8 + 4) = o1;
    *(__half2*)(ph + tid * 8)     = __floats2half2_rn(o0.x, o0.y);
    *(__half2*)(ph + tid * 8 + 2) = __floats2half2_rn(o0.z, o0.w);
    *(__half2*)(ph + tid * 8 + 4) = __floats2half2_rn(o1.x, o1.y);
    *(__half2*)(ph + tid * 8 + 6) = __floats2half2_rn(o1.z, o1.w);
}

// residual + layernorm (warp-shuffle reductions, float4 I/O); writes out[:, D:2D]
__global__ void ln_concat(const float* __restrict__ x, const float* __restrict__ att,
                          const float* __restrict__ gamma, const float* __restrict__ beta,
                          float* __restrict__ out)
{
    long long row = blockIdx.x;
    const float* xr = x + row * Dd;
    const float* ar = att + row * Dd;
    float* o = out + row * (2 * Dd);
    __shared__ float red[8];
    const int tid = threadIdx.x;
    const int lane = tid & 31, warp = tid >> 5;
    const int c0 = tid * 4;

    float4 xv = *(const float4*)(xr + c0);
    float4 av = *(const float4*)(ar + c0);
    float h[4] = {xv.x + av.x, xv.y + av.y, xv.z + av.z, xv.w + av.w};
    float s = h[0] + h[1] + h[2] + h[3];
#pragma unroll
    for (int st = 16; st > 0; st >>= 1)
        s += __shfl_xor_sync(0xffffffffu, s, st);
    if (lane == 0) red[warp] = s;
    __syncthreads();
    s = red[0];
#pragma unroll
    for (int w = 1; w < 8; w++) s += red[w];
    float mu = s * (1.0f / Dd);
    __syncthreads();

    float v = 0.0f;
#pragma unroll
    for (int i = 0; i < 4; i++) { float d = h[i] - mu; v += d * d; }
#pragma unroll
    for (int st = 16; st > 0; st >>= 1)
        v += __shfl_xor_sync(0xffffffffu, v, st);
    if (lane == 0) red[warp] = v;
    __syncthreads();
    v = red[0];
#pragma unroll
    for (int w = 1; w < 8; w++) v += red[w];
    float rstd = rsqrtf(v * (1.0f / Dd) + 1e-5f);

    float4 gv = *(const float4*)(gamma + c0);
    float4 bv = *(const float4*)(beta + c0);
    float4 ov;
    ov.x = (h[0] - mu) * rstd * gv.x + bv.x;
    ov.y = (h[1] - mu) * rstd * gv.y + bv.y;
    ov.z = (h[2] - mu) * rstd * gv.z + bv.z;
    ov.w = (h[3] - mu) * rstd * gv.w + bv.w;
    *(float4*)(o + Dd + c0) = ov;
}

// ------------------------------- launcher -----------------------------------
extern "C" void kernel_launch(void* const* d_in, const int* in_sizes, int n_in,
                              void* d_out, int out_size)
{
    const float* x     = (const float*)d_in[0];
    const float* Wk    = (const float*)d_in[1];
    const float* bk    = (const float*)d_in[2];
    const float* Wq    = (const float*)d_in[3];
    const float* bq    = (const float*)d_in[4];
    const float* Wv    = (const float*)d_in[5];
    const float* bv    = (const float*)d_in[6];
    const float* gamma = (const float*)d_in[7];
    const float* beta  = (const float*)d_in[8];

    float* out = (float*)d_out;
    float* att = out + (long long)MT * 2 * Dd;
    float* wgt = att + (long long)MT * Dd;

    __half *x16, *W16, *QK, *Vt, *s16, *w16;
    float* bqk;
    cudaGetSymbolAddress((void**)&x16, g_x16);
    cudaGetSymbolAddress((void**)&W16, g_W16);
    cudaGetSymbolAddress((void**)&bqk, g_b);
    cudaGetSymbolAddress((void**)&QK,  g_QK);
    cudaGetSymbolAddress((void**)&Vt,  g_Vt);
    cudaGetSymbolAddress((void**)&s16, g_s16);
    cudaGetSymbolAddress((void**)&w16, g_w16);

    cudaFuncSetAttribute(mma_gemm<0, 0>, cudaFuncAttributeMaxDynamicSharedMemorySize, SMEM_BYTES);
    cudaFuncSetAttribute(mma_gemm<1, 0>, cudaFuncAttributeMaxDynamicSharedMemorySize, SMEM_BYTES);
    cudaFuncSetAttribute(mma_gemm<1, 1>, cudaFuncAttributeMaxDynamicSharedMemorySize, SMEM_BYTES);
    cudaFuncSetAttribute(mma_gemm<1, 2>, cudaFuncAttributeMaxDynamicSharedMemorySize, SMEM_BYTES);

    cudaStream_t s1 = g_ss.s1;

    // ---- fork: side stream handles weight prep, then Vt GEMM ----
    cudaEventRecord(g_ss.e0, 0);
    cudaStreamWaitEvent(s1, g_ss.e0, 0);

    // side stream: bias pack + weight transposes (independent of x16)
    copy_bias<<<2, Dd, 0, s1>>>(bq, bk, bqk);
    {
        dim3 g(Dd / 32, Dd / 32, 3), b(32, 8);
        transW<<<g, b, 0, s1>>>(Wq, Wk, Wv, W16);
    }
    cudaEventRecord(g_ss.eW, s1);             // W16 + bqk ready

    // main stream: x conversion (+ concat x half)
    cvt_x<<<MT * Dd / 4096, 1024>>>(x, x16, out);
    cudaEventRecord(g_ss.e1, 0);              // x16 ready

    // side stream: Vt[b][d,n] = Wv^T @ x_b^T + bv  (needs x16 + W16)
    cudaStreamWaitEvent(s1, g_ss.e1, 0);
    {
        dim3 g(Nn / BNm, Dd / BMm, Bb), b(256);
        mma_gemm<1, 2><<<g, b, SMEM_BYTES, s1>>>(W16 + (size_t)2 * Dd * Dd, x16, bv,
                                                 nullptr, Vt,
                                                 Dd, Nn,
                                                 0, (long long)Nn * Dd, (long long)Dd * Nn,
                                                 0, 1.0f);
    }
    cudaEventRecord(g_ss.eV, s1);             // Vt ready

    // main stream: QK projection (needs W16 + bqk from side stream)
    cudaStreamWaitEvent(0, g_ss.eW, 0);
    {
        dim3 g(Dd / BNm, MT / BMm, 2), b(256);
        mma_gemm<1, 1><<<g, b, SMEM_BYTES>>>(x16, W16, bqk, nullptr, QK,
                                             Dd, Dd,
                                             0, (long long)Dd * Dd, (long long)MT * Dd,
                                             Dd, 1.0f);
    }

    // main stream: scores = Q @ K^T / 32 -> s16 (fp16)
    {
        dim3 g(Nn / BNm, Nn / BMm, Bb), b(256);
        mma_gemm<1, 0><<<g, b, SMEM_BYTES>>>(QK, QK + (size_t)MT * Dd, nullptr,
                                             nullptr, s16,
                                             Dd, Nn,
                                             (long long)Nn * Dd, (long long)Nn * Dd,
                                             (long long)Nn * Nn, 0, 1.0f / 32.0f);
    }

    // main stream: softmax (fp16 scores -> fp32 weight + fp16 copy)
    softmax_split<<<Bb * Nn, 256>>>(s16, wgt, w16);

    // join: attn needs Vt from side stream
    cudaStreamWaitEvent(0, g_ss.eV, 0);
    {
        dim3 g(Dd / BNm, Nn / BMm, Bb), b(256);
        mma_gemm<0, 0><<<g, b, SMEM_BYTES>>>(w16, Vt, nullptr, att, nullptr,
                                             Nn, Dd,
                                             (long long)Nn * Nn, (long long)Nn * Dd,
                                             (long long)Nn * Dd, 0, 1.0f);
    }

    // main stream: out[:, D:2D] = LN(x + att)
    ln_concat<<<Bb * Nn, 256>>>(x, att, gamma, beta, out);
}

// round 16
// speedup vs baseline: 1.1560x; 1.0226x over previous
#include <cuda_runtime.h>
#include <cuda_fp16.h>
#include <math.h>
#include <stdint.h>

// ---------------------------------------------------------------------------
// attention_83932250898666 : B=4, N=2048, D=1024
// d_out layout (float32):
//   [0, 16777216)        out   = concat(x, LN(x+att))   [B,N,2D]
//   [16777216, 25165824) att_score                      [B,N,D]
//   [25165824, 41943040) weight = softmax(QK^T/32)      [B,N,N]
// GEMMs: single-pass fp16 mma.sync (HMMA), fp32 accumulate.
// Round 16: batch-halved pipeline — scores/softmax/attn/ln for batches {0,1}
//           run on a second stream overlapping the {2,3} chain on main;
//           Vt path on s1 as in round 15. Kernels identical to round 15.
// ---------------------------------------------------------------------------

#define Bb 4
#define Nn 2048
#define Dd 1024
#define MT (Bb*Nn)   // 8192

// ------------------------- device scratch (no allocs) ----------------------
__device__ __half g_x16[(size_t)MT * Dd];
__device__ __half g_W16[(size_t)3 * Dd * Dd];      // [z][n][k] transposed weights
__device__ float  g_b[2 * Dd];                     // biases q,k
__device__ __half g_QK[(size_t)2 * MT * Dd];       // Q | K
__device__ __half g_Vt[(size_t)MT * Dd];           // per-batch V^T [b][d][n]
__device__ __half g_s16[(size_t)Bb * Nn * Nn];     // raw scores fp16
__device__ __half g_w16[(size_t)Bb * Nn * Nn];     // softmax weights fp16

// ---------------- streams/events (created at load, before checkpoints) -----
struct SideStream {
    cudaStream_t s1, s2;
    cudaEvent_t e0, e1, eW, eV, eQA, eLA;
    SideStream() {
        cudaStreamCreateWithFlags(&s1, cudaStreamNonBlocking);
        cudaStreamCreateWithFlags(&s2, cudaStreamNonBlocking);
        cudaEventCreateWithFlags(&e0,  cudaEventDisableTiming);
        cudaEventCreateWithFlags(&e1,  cudaEventDisableTiming);
        cudaEventCreateWithFlags(&eW,  cudaEventDisableTiming);
        cudaEventCreateWithFlags(&eV,  cudaEventDisableTiming);
        cudaEventCreateWithFlags(&eQA, cudaEventDisableTiming);
        cudaEventCreateWithFlags(&eLA, cudaEventDisableTiming);
    }
};
static SideStream g_ss;

// ------------------------------ PTX helpers --------------------------------
__device__ __forceinline__ uint32_t smem_u32(const void* p) {
    uint32_t a;
    asm("{ .reg .u64 t; cvta.to.shared.u64 t, %1; cvt.u32.u64 %0, t; }" : "=r"(a) : "l"(p));
    return a;
}

#define CP16(dst, src) \
    asm volatile("cp.async.cg.shared.global [%0], [%1], 16;" :: "r"(dst), "l"(src))
#define CP_COMMIT() asm volatile("cp.async.commit_group;" ::: "memory")
#define CP_WAIT1()  asm volatile("cp.async.wait_group 1;" ::: "memory")

#define LDSM4(R0, R1, R2, R3, A) \
    asm volatile("ldmatrix.sync.aligned.m8n8.x4.shared.b16 {%0,%1,%2,%3}, [%4];" \
                 : "=r"(R0), "=r"(R1), "=r"(R2), "=r"(R3) : "r"(A))

#define MMAH(D, A0, A1, A2, A3, B0, B1) \
    asm volatile("mma.sync.aligned.m16n8k16.row.col.f32.f16.f16.f32 " \
                 "{%0,%1,%2,%3},{%4,%5,%6,%7},{%8,%9},{%0,%1,%2,%3};" \
                 : "+f"((D)[0]), "+f"((D)[1]), "+f"((D)[2]), "+f"((D)[3]) \
                 : "r"(A0), "r"(A1), "r"(A2), "r"(A3), "r"(B0), "r"(B1))

// ------------------------------- MMA GEMM ----------------------------------
// C[M,N] = alpha*(A @ Bmat^T)(+bias). A:[M,K] fp16 (ld=K), Bmat:[N,K] fp16 (ld=K).
// Block 128x128, 8 warps (4m x 2n), warp tile 32x64, K-chunk 64, 3-stage cp.async.
#define BMm 128
#define BNm 128
#define BKm 64
#define LDSm 72                          // padded row length in halves (144B)
#define OPA (128 * LDSm * 2)             // 18432 B
#define STGB (2 * OPA)                   // 36864 B
#define NSTAGE 3
#define SMEM_BYTES (NSTAGE * STGB)       // 110592

// EPI: 0 fp32 out, 1 fp16 out.  BIASMODE: 0 none, 1 per-col, 2 per-row.
template<int EPI, int BIASMODE>
__global__ __launch_bounds__(256, 2)
void mma_gemm(const __half* __restrict__ A, const __half* __restrict__ B,
              const float* __restrict__ bias,
              float* __restrict__ Cf, __half* __restrict__ Ch,
              int K, int ldc,
              long long sA, long long sB, long long sC, long long sBias, float alpha)
{
    extern __shared__ char smem[];
    const uint32_t sbase = smem_u32(smem);
    const int tid  = threadIdx.x;
    const int wid  = tid >> 5;
    const int lane = tid & 31;
    const int wy = wid >> 1;            // 0..3  (m, 32 rows each)
    const int wx = wid & 1;             // 0..1  (n, 64 cols each)
    const int m0 = blockIdx.y * BMm;
    const int n0 = blockIdx.x * BNm;
    A += (long long)blockIdx.z * sA;
    B += (long long)blockIdx.z * sB;
    if (BIASMODE) bias += (long long)blockIdx.z * sBias;

    float acc[2][8][4];
#pragma unroll
    for (int i = 0; i < 2; i++)
#pragma unroll
        for (int j = 0; j < 8; j++)
#pragma unroll
            for (int q = 0; q < 4; q++) acc[i][j][q] = 0.0f;

    const int nch = K / BKm;

    // hoisted per-thread gmem pointers and smem store offset for cp.async
    const int rA = tid >> 3, cA = tid & 7;
    const __half* gA = A + (long long)(m0 + rA) * K + cA * 8;
    const __half* gB = B + (long long)(n0 + rA) * K + cA * 8;
    const uint32_t soff = (uint32_t)(rA * LDSm + cA * 8) * 2;
    const long long gstep = (long long)32 * K;                 // 32 rows

    // full-stage load (prologue only)
    auto load_stage = [&](uint32_t sb, int k0) {
#pragma unroll
        for (int t = 0; t < 4; t++)
            CP16(sb + soff + t * (32 * LDSm * 2), gA + t * gstep + k0);
#pragma unroll
        for (int t = 0; t < 4; t++)
            CP16(sb + OPA + soff + t * (32 * LDSm * 2), gB + t * gstep + k0);
    };

    // 1/8th of a stage load; p in [0,8)
    auto load_part = [&](uint32_t sb, int k0, int p) {
        if (p < 4)
            CP16(sb + soff + p * (32 * LDSm * 2), gA + p * gstep + k0);
        else
            CP16(sb + OPA + soff + (p - 4) * (32 * LDSm * 2), gB + (p - 4) * gstep + k0);
    };

    load_stage(sbase, 0);           CP_COMMIT();
    load_stage(sbase + STGB, BKm);  CP_COMMIT();

    // ldmatrix lane base addresses (smem-stage-relative)
    const int arow = (lane & 7) + ((lane >> 3) & 1) * 8;   // 0..15
    const int acol = (lane >> 4) * 8;                      // 0 / 8
    const int brow = (lane & 7) + (lane >> 4) * 8;
    const int bcol = ((lane >> 3) & 1) * 8;
    const uint32_t baseA = (uint32_t)((32 * wy + arow) * LDSm + acol) * 2;
    const uint32_t baseB = (uint32_t)((64 * wx + brow) * LDSm + bcol) * 2 + OPA;

    uint32_t af[2][2][4];      // A fragments, double buffered over ks
    uint32_t bf[2][4][2];      // B fragments, rolling buffer per half-ks (4 j each)

    auto ldA = [&](int buf, uint32_t sb, int ks) {
#pragma unroll
        for (int i = 0; i < 2; i++) {
            uint32_t aoff = sb + baseA + (uint32_t)(16 * i * LDSm + ks * 16) * 2;
            LDSM4(af[buf][i][0], af[buf][i][1], af[buf][i][2], af[buf][i][3], aoff);
        }
    };
    auto ldB = [&](int buf, uint32_t sb, int ks, int jh) {
#pragma unroll
        for (int jpp = 0; jpp < 2; jpp++) {
            uint32_t boff = sb + baseB
                          + (uint32_t)(16 * (2 * jh + jpp) * LDSm + ks * 16) * 2;
            LDSM4(bf[buf][2*jpp][0], bf[buf][2*jpp][1], bf[buf][2*jpp+1][0], bf[buf][2*jpp+1][1],
                  boff);
        }
    };

    uint32_t sb_cur = sbase;                  // stage for chunk c
    uint32_t sb_pf  = sbase + 2 * STGB;       // stage for chunk c+2
    int k_pf = 2 * BKm;                       // k0 for chunk c+2

    for (int c = 0; c < nch; c++) {
        CP_WAIT1();
        __syncthreads();
        const uint32_t sb = sb_cur;
        const bool pf = (c + 2 < nch);
        const uint32_t s2 = sb_pf;
        const int k2 = k_pf;

        ldA(0, sb, 0);
        ldB(0, sb, 0, 0);
#pragma unroll
        for (int idx = 0; idx < 8; idx++) {          // ks = idx>>1, jh = idx&1
            const int ks = idx >> 1, jh = idx & 1;
            if (idx < 7) ldB((idx + 1) & 1, sb, (idx + 1) >> 1, (idx + 1) & 1);
            if (jh == 0 && ks < 3) ldA((ks + 1) & 1, sb, ks + 1);
            if (pf) load_part(s2, k2, idx);
            const int ab = ks & 1, bb = idx & 1;
#pragma unroll
            for (int i = 0; i < 2; i++)
#pragma unroll
                for (int jj = 0; jj < 4; jj++)
                    MMAH(acc[i][jh * 4 + jj],
                         af[ab][i][0], af[ab][i][1], af[ab][i][2], af[ab][i][3],
                         bf[bb][jj][0], bf[bb][jj][1]);
        }
        CP_COMMIT();
        // rotate stage pointers (no modulo)
        sb_cur += STGB; if (sb_cur == sbase + NSTAGE * STGB) sb_cur = sbase;
        sb_pf  += STGB; if (sb_pf  == sbase + NSTAGE * STGB) sb_pf  = sbase;
        k_pf   += BKm;
    }

    // ------------------------------ epilogue --------------------------------
    const int g  = lane >> 2;
    const int t4 = lane & 3;
    const long long cb = (long long)blockIdx.z * sC;
#pragma unroll
    for (int i = 0; i < 2; i++) {
#pragma unroll
        for (int j = 0; j < 8; j++) {
            int mrow = m0 + 32 * wy + 16 * i + g;
            int ncol = n0 + 64 * wx + 8 * j + 2 * t4;
            float v00 = acc[i][j][0] * alpha, v01 = acc[i][j][1] * alpha;
            float v10 = acc[i][j][2] * alpha, v11 = acc[i][j][3] * alpha;
            long long o0 = cb + (long long)mrow * ldc + ncol;
            long long o1 = cb + (long long)(mrow + 8) * ldc + ncol;
            if (BIASMODE == 1) {
                float b0 = bias[ncol], b1 = bias[ncol + 1];
                v00 += b0; v01 += b1; v10 += b0; v11 += b1;
            } else if (BIASMODE == 2) {
                float br0 = bias[mrow], br1 = bias[mrow + 8];
                v00 += br0; v01 += br0; v10 += br1; v11 += br1;
            }
            if (EPI == 0) {
                *(float2*)(Cf + o0) = make_float2(v00, v01);
                *(float2*)(Cf + o1) = make_float2(v10, v11);
            } else {
                *(__half2*)(Ch + o0) = __floats2half2_rn(v00, v01);
                *(__half2*)(Ch + o1) = __floats2half2_rn(v10, v11);
            }
        }
    }
}

// --------------------------- aux kernels ------------------------------------
// fp32 -> fp16 AND copy x into out[:, 0:D] (concat first half, off critical path)
__global__ void cvt_x(const float* __restrict__ in, __half* __restrict__ out16,
                      float* __restrict__ outx)
{
    long long i = ((long long)blockIdx.x * blockDim.x + threadIdx.x) * 4;
    float4 v = *(const float4*)(in + i);
    *(__half2*)(out16 + i)     = __floats2half2_rn(v.x, v.y);
    *(__half2*)(out16 + i + 2) = __floats2half2_rn(v.z, v.w);
    long long row = i >> 10;              // / Dd
    long long col = i & (Dd - 1);
    *(float4*)(outx + row * (2 * Dd) + col) = v;
}

__global__ void copy_bias(const float* __restrict__ b0, const float* __restrict__ b1,
                          float* __restrict__ dst)
{
    int z = blockIdx.x;
    const float* s = (z == 0) ? b0 : b1;
    dst[z * Dd + threadIdx.x] = s[threadIdx.x];
}

// Wt[n,k] = W[k,n] fp16 ; z selects which W
__global__ void transW(const float* __restrict__ W0, const float* __restrict__ W1,
                       const float* __restrict__ W2, __half* __restrict__ out)
{
    __shared__ float t[32][33];
    const float* W = (blockIdx.z == 0) ? W0 : (blockIdx.z == 1) ? W1 : W2;
    __half* o = out + (size_t)blockIdx.z * Dd * Dd;
    int bx = blockIdx.x * 32, by = blockIdx.y * 32;
    int tx = threadIdx.x, ty = threadIdx.y;
#pragma unroll
    for (int r = 0; r < 4; r++)
        t[ty + 8 * r][tx] = W[(long long)(by + ty + 8 * r) * Dd + bx + tx];
    __syncthreads();
#pragma unroll
    for (int r = 0; r < 4; r++)
        o[(long long)(bx + ty + 8 * r) * Dd + by + tx] = __float2half_rn(t[tx][ty + 8 * r]);
}

// softmax: reads raw fp16 scores, computes fp32, writes fp32 weight + fp16 copy
__global__ void softmax_split(const __half* __restrict__ S, float* __restrict__ W,
                              __half* __restrict__ wh)
{
    long long row = blockIdx.x;
    const __half* ps = S + row * (long long)Nn;
    float* p = W + row * (long long)Nn;
    __half* ph = wh + row * (long long)Nn;
    __shared__ float red[8];
    const int tid = threadIdx.x;
    const int lane = tid & 31, warp = tid >> 5;

    float e[8];
    {
        uint4 raw = *(const uint4*)(ps + tid * 8);     // 8 halves
        __half2 h0 = *(__half2*)&raw.x;
        __half2 h1 = *(__half2*)&raw.y;
        __half2 h2 = *(__half2*)&raw.z;
        __half2 h3 = *(__half2*)&raw.w;
        float2 f0 = __half22float2(h0), f1 = __half22float2(h1);
        float2 f2 = __half22float2(h2), f3 = __half22float2(h3);
        e[0]=f0.x; e[1]=f0.y; e[2]=f1.x; e[3]=f1.y;
        e[4]=f2.x; e[5]=f2.y; e[6]=f3.x; e[7]=f3.y;
    }
    float mx = e[0];
#pragma unroll
    for (int i = 1; i < 8; i++) mx = fmaxf(mx, e[i]);
#pragma unroll
    for (int s = 16; s > 0; s >>= 1)
        mx = fmaxf(mx, __shfl_xor_sync(0xffffffffu, mx, s));
    if (lane == 0) red[warp] = mx;
    __syncthreads();
    mx = red[0];
#pragma unroll
    for (int w = 1; w < 8; w++) mx = fmaxf(mx, red[w]);
    __syncthreads();

    float sum = 0.0f;
#pragma unroll
    for (int i = 0; i < 8; i++) { e[i] = expf(e[i] - mx); sum += e[i]; }
#pragma unroll
    for (int s = 16; s > 0; s >>= 1)
        sum += __shfl_xor_sync(0xffffffffu, sum, s);
    if (lane == 0) red[warp] = sum;
    __syncthreads();
    sum = red[0];
#pragma unroll
    for (int w = 1; w < 8; w++) sum += red[w];
    float inv = 1.0f / sum;

    float4 o0, o1;
    o0.x = e[0]*inv; o0.y = e[1]*inv; o0.z = e[2]*inv; o0.w = e[3]*inv;
    o1.x = e[4]*inv; o1.y = e[5]*inv; o1.z = e[6]*inv; o1.w = e[7]*inv;
    *(float4*)(p + tid * 8)     = o0;
    *(float4*)(p + tid * 8 + 4) = o1;
    *(__half2*)(ph + tid * 8)     = __floats2half2_rn(o0.x, o0.y);
    *(__half2*)(ph + tid * 8 + 2) = __floats2half2_rn(o0.z, o0.w);
    *(__half2*)(ph + tid * 8 + 4) = __floats2half2_rn(o1.x, o1.y);
    *(__half2*)(ph + tid * 8 + 6) = __floats2half2_rn(o1.z, o1.w);
}

// residual + layernorm (warp-shuffle reductions, float4 I/O); writes out[:, D:2D]
__global__ void ln_concat(const float* __restrict__ x, const float* __restrict__ att,
                          const float* __restrict__ gamma, const float* __restrict__ beta,
                          float* __restrict__ out)
{
    long long row = blockIdx.x;
    const float* xr = x + row * Dd;
    const float* ar = att + row * Dd;
    float* o = out + row * (2 * Dd);
    __shared__ float red[8];
    const int tid = threadIdx.x;
    const int lane = tid & 31, warp = tid >> 5;
    const int c0 = tid * 4;

    float4 xv = *(const float4*)(xr + c0);
    float4 av = *(const float4*)(ar + c0);
    float h[4] = {xv.x + av.x, xv.y + av.y, xv.z + av.z, xv.w + av.w};
    float s = h[0] + h[1] + h[2] + h[3];
#pragma unroll
    for (int st = 16; st > 0; st >>= 1)
        s += __shfl_xor_sync(0xffffffffu, s, st);
    if (lane == 0) red[warp] = s;
    __syncthreads();
    s = red[0];
#pragma unroll
    for (int w = 1; w < 8; w++) s += red[w];
    float mu = s * (1.0f / Dd);
    __syncthreads();

    float v = 0.0f;
#pragma unroll
    for (int i = 0; i < 4; i++) { float d = h[i] - mu; v += d * d; }
#pragma unroll
    for (int st = 16; st > 0; st >>= 1)
        v += __shfl_xor_sync(0xffffffffu, v, st);
    if (lane == 0) red[warp] = v;
    __syncthreads();
    v = red[0];
#pragma unroll
    for (int w = 1; w < 8; w++) v += red[w];
    float rstd = rsqrtf(v * (1.0f / Dd) + 1e-5f);

    float4 gv = *(const float4*)(gamma + c0);
    float4 bv = *(const float4*)(beta + c0);
    float4 ov;
    ov.x = (h[0] - mu) * rstd * gv.x + bv.x;
    ov.y = (h[1] - mu) * rstd * gv.y + bv.y;
    ov.z = (h[2] - mu) * rstd * gv.z + bv.z;
    ov.w = (h[3] - mu) * rstd * gv.w + bv.w;
    *(float4*)(o + Dd + c0) = ov;
}

// ------------------------------- launcher -----------------------------------
extern "C" void kernel_launch(void* const* d_in, const int* in_sizes, int n_in,
                              void* d_out, int out_size)
{
    const float* x     = (const float*)d_in[0];
    const float* Wk    = (const float*)d_in[1];
    const float* bk    = (const float*)d_in[2];
    const float* Wq    = (const float*)d_in[3];
    const float* bq    = (const float*)d_in[4];
    const float* Wv    = (const float*)d_in[5];
    const float* bv    = (const float*)d_in[6];
    const float* gamma = (const float*)d_in[7];
    const float* beta  = (const float*)d_in[8];

    float* out = (float*)d_out;
    float* att = out + (long long)MT * 2 * Dd;
    float* wgt = att + (long long)MT * Dd;

    __half *x16, *W16, *QK, *Vt, *s16, *w16;
    float* bqk;
    cudaGetSymbolAddress((void**)&x16, g_x16);
    cudaGetSymbolAddress((void**)&W16, g_W16);
    cudaGetSymbolAddress((void**)&bqk, g_b);
    cudaGetSymbolAddress((void**)&QK,  g_QK);
    cudaGetSymbolAddress((void**)&Vt,  g_Vt);
    cudaGetSymbolAddress((void**)&s16, g_s16);
    cudaGetSymbolAddress((void**)&w16, g_w16);

    cudaFuncSetAttribute(mma_gemm<0, 0>, cudaFuncAttributeMaxDynamicSharedMemorySize, SMEM_BYTES);
    cudaFuncSetAttribute(mma_gemm<1, 0>, cudaFuncAttributeMaxDynamicSharedMemorySize, SMEM_BYTES);
    cudaFuncSetAttribute(mma_gemm<1, 1>, cudaFuncAttributeMaxDynamicSharedMemorySize, SMEM_BYTES);
    cudaFuncSetAttribute(mma_gemm<1, 2>, cudaFuncAttributeMaxDynamicSharedMemorySize, SMEM_BYTES);

    cudaStream_t s1 = g_ss.s1, s2 = g_ss.s2;

    const size_t halfX  = (size_t)2 * Nn * Dd;    // 2 batches of x/Q/K/att rows
    const size_t halfS  = (size_t)2 * Nn * Nn;    // 2 batches of scores/weights
    const long long sQK = (long long)Nn * Dd;     // per-batch stride Q/K/att
    const long long sW  = (long long)Nn * Nn;     // per-batch stride scores

    // ---- fork both side streams from origin ----
    cudaEventRecord(g_ss.e0, 0);
    cudaStreamWaitEvent(s1, g_ss.e0, 0);
    cudaStreamWaitEvent(s2, g_ss.e0, 0);

    // s1: bias pack + weight transposes, then Vt
    copy_bias<<<2, Dd, 0, s1>>>(bq, bk, bqk);
    {
        dim3 g(Dd / 32, Dd / 32, 3), b(32, 8);
        transW<<<g, b, 0, s1>>>(Wq, Wk, Wv, W16);
    }
    cudaEventRecord(g_ss.eW, s1);

    // main: x conversion (+ concat x half)
    cvt_x<<<MT * Dd / 4096, 1024>>>(x, x16, out);
    cudaEventRecord(g_ss.e1, 0);

    // s1: Vt = Wv^T @ x^T + bv (per batch)
    cudaStreamWaitEvent(s1, g_ss.e1, 0);
    {
        dim3 g(Nn / BNm, Dd / BMm, Bb), b(256);
        mma_gemm<1, 2><<<g, b, SMEM_BYTES, s1>>>(W16 + (size_t)2 * Dd * Dd, x16, bv,
                                                 nullptr, Vt,
                                                 Dd, Nn,
                                                 0, sQK, (long long)Dd * Nn, 0, 1.0f);
    }
    cudaEventRecord(g_ss.eV, s1);

    // main: QK projection, half A (batches 0,1): rows 0..4095
    cudaStreamWaitEvent(0, g_ss.eW, 0);
    {
        dim3 g(Dd / BNm, 32, 2), b(256);
        mma_gemm<1, 1><<<g, b, SMEM_BYTES>>>(x16, W16, bqk, nullptr, QK,
                                             Dd, Dd,
                                             0, (long long)Dd * Dd, (long long)MT * Dd,
                                             Dd, 1.0f);
    }
    cudaEventRecord(g_ss.eQA, 0);

    // main: QK projection, half B (batches 2,3)
    {
        dim3 g(Dd / BNm, 32, 2), b(256);
        mma_gemm<1, 1><<<g, b, SMEM_BYTES>>>(x16 + halfX, W16, bqk, nullptr, QK + halfX,
                                             Dd, Dd,
                                             0, (long long)Dd * Dd, (long long)MT * Dd,
                                             Dd, 1.0f);
    }

    // s2: half-A chain (batches 0,1): scores -> softmax -> attn -> ln
    cudaStreamWaitEvent(s2, g_ss.eQA, 0);
    {
        dim3 g(Nn / BNm, Nn / BMm, 2), b(256);
        mma_gemm<1, 0><<<g, b, SMEM_BYTES, s2>>>(QK, QK + (size_t)MT * Dd, nullptr,
                                                 nullptr, s16,
                                                 Dd, Nn, sQK, sQK, sW, 0, 1.0f / 32.0f);
    }
    softmax_split<<<2 * Nn, 256, 0, s2>>>(s16, wgt, w16);
    cudaStreamWaitEvent(s2, g_ss.eV, 0);
    {
        dim3 g(Dd / BNm, Nn / BMm, 2), b(256);
        mma_gemm<0, 0><<<g, b, SMEM_BYTES, s2>>>(w16, Vt, nullptr, att, nullptr,
                                                 Nn, Dd, sW, sQK, sQK, 0, 1.0f);
    }
    ln_concat<<<2 * Nn, 256, 0, s2>>>(x, att, gamma, beta, out);
    cudaEventRecord(g_ss.eLA, s2);

    // main: half-B chain (batches 2,3)
    {
        dim3 g(Nn / BNm, Nn / BMm, 2), b(256);
        mma_gemm<1, 0><<<g, b, SMEM_BYTES>>>(QK + halfX, QK + (size_t)MT * Dd + halfX,
                                             nullptr, nullptr, s16 + halfS,
                                             Dd, Nn, sQK, sQK, sW, 0, 1.0f / 32.0f);
    }
    softmax_split<<<2 * Nn, 256>>>(s16 + halfS, wgt + halfS, w16 + halfS);
    cudaStreamWaitEvent(0, g_ss.eV, 0);
    {
        dim3 g(Dd / BNm, Nn / BMm, 2), b(256);
        mma_gemm<0, 0><<<g, b, SMEM_BYTES>>>(w16 + halfS, Vt + halfX, nullptr,
                                             att + halfX, nullptr,
                                             Nn, Dd, sW, sQK, sQK, 0, 1.0f);
    }
    // join s2 before the final main-stream kernel
    cudaStreamWaitEvent(0, g_ss.eLA, 0);
    ln_concat<<<2 * Nn, 256>>>(x + halfX, att + halfX, gamma, beta,
                               out + (size_t)2 * Nn * 2 * Dd);
}

// round 17
// speedup vs baseline: 1.1647x; 1.0075x over previous
#include <cuda_runtime.h>
#include <cuda_fp16.h>
#include <math.h>
#include <stdint.h>

// ---------------------------------------------------------------------------
// attention_83932250898666 : B=4, N=2048, D=1024
// d_out layout (float32):
//   [0, 16777216)        out   = concat(x, LN(x+att))   [B,N,2D]
//   [16777216, 25165824) att_score                      [B,N,D]
//   [25165824, 41943040) weight = softmax(QK^T/32)      [B,N,N]
// GEMMs: single-pass fp16 mma.sync (HMMA), fp32 accumulate.
// Round 17: finer pipeline — cvt_x split across streams; per-batch (4-way)
//           scores/softmax/attn/ln chains on 4 streams. Kernels identical.
// ---------------------------------------------------------------------------

#define Bb 4
#define Nn 2048
#define Dd 1024
#define MT (Bb*Nn)   // 8192

// ------------------------- device scratch (no allocs) ----------------------
__device__ __half g_x16[(size_t)MT * Dd];
__device__ __half g_W16[(size_t)3 * Dd * Dd];      // [z][n][k] transposed weights
__device__ float  g_b[2 * Dd];                     // biases q,k
__device__ __half g_QK[(size_t)2 * MT * Dd];       // Q | K
__device__ __half g_Vt[(size_t)MT * Dd];           // per-batch V^T [b][d][n]
__device__ __half g_s16[(size_t)Bb * Nn * Nn];     // raw scores fp16
__device__ __half g_w16[(size_t)Bb * Nn * Nn];     // softmax weights fp16

// ---------------- streams/events (created at load, before checkpoints) -----
struct SideStream {
    cudaStream_t s1, s2, s3;
    cudaEvent_t e0, e1a, e1b, eW, eV, eQA, eQB, eL0, eL1, eL3;
    SideStream() {
        cudaStreamCreateWithFlags(&s1, cudaStreamNonBlocking);
        cudaStreamCreateWithFlags(&s2, cudaStreamNonBlocking);
        cudaStreamCreateWithFlags(&s3, cudaStreamNonBlocking);
        cudaEventCreateWithFlags(&e0,  cudaEventDisableTiming);
        cudaEventCreateWithFlags(&e1a, cudaEventDisableTiming);
        cudaEventCreateWithFlags(&e1b, cudaEventDisableTiming);
        cudaEventCreateWithFlags(&eW,  cudaEventDisableTiming);
        cudaEventCreateWithFlags(&eV,  cudaEventDisableTiming);
        cudaEventCreateWithFlags(&eQA, cudaEventDisableTiming);
        cudaEventCreateWithFlags(&eQB, cudaEventDisableTiming);
        cudaEventCreateWithFlags(&eL0, cudaEventDisableTiming);
        cudaEventCreateWithFlags(&eL1, cudaEventDisableTiming);
        cudaEventCreateWithFlags(&eL3, cudaEventDisableTiming);
    }
};
static SideStream g_ss;

// ------------------------------ PTX helpers --------------------------------
__device__ __forceinline__ uint32_t smem_u32(const void* p) {
    uint32_t a;
    asm("{ .reg .u64 t; cvta.to.shared.u64 t, %1; cvt.u32.u64 %0, t; }" : "=r"(a) : "l"(p));
    return a;
}

#define CP16(dst, src) \
    asm volatile("cp.async.cg.shared.global [%0], [%1], 16;" :: "r"(dst), "l"(src))
#define CP_COMMIT() asm volatile("cp.async.commit_group;" ::: "memory")
#define CP_WAIT1()  asm volatile("cp.async.wait_group 1;" ::: "memory")

#define LDSM4(R0, R1, R2, R3, A) \
    asm volatile("ldmatrix.sync.aligned.m8n8.x4.shared.b16 {%0,%1,%2,%3}, [%4];" \
                 : "=r"(R0), "=r"(R1), "=r"(R2), "=r"(R3) : "r"(A))

#define MMAH(D, A0, A1, A2, A3, B0, B1) \
    asm volatile("mma.sync.aligned.m16n8k16.row.col.f32.f16.f16.f32 " \
                 "{%0,%1,%2,%3},{%4,%5,%6,%7},{%8,%9},{%0,%1,%2,%3};" \
                 : "+f"((D)[0]), "+f"((D)[1]), "+f"((D)[2]), "+f"((D)[3]) \
                 : "r"(A0), "r"(A1), "r"(A2), "r"(A3), "r"(B0), "r"(B1))

// ------------------------------- MMA GEMM ----------------------------------
// C[M,N] = alpha*(A @ Bmat^T)(+bias). A:[M,K] fp16 (ld=K), Bmat:[N,K] fp16 (ld=K).
// Block 128x128, 8 warps (4m x 2n), warp tile 32x64, K-chunk 64, 3-stage cp.async.
#define BMm 128
#define BNm 128
#define BKm 64
#define LDSm 72                          // padded row length in halves (144B)
#define OPA (128 * LDSm * 2)             // 18432 B
#define STGB (2 * OPA)                   // 36864 B
#define NSTAGE 3
#define SMEM_BYTES (NSTAGE * STGB)       // 110592

// EPI: 0 fp32 out, 1 fp16 out.  BIASMODE: 0 none, 1 per-col, 2 per-row.
template<int EPI, int BIASMODE>
__global__ __launch_bounds__(256, 2)
void mma_gemm(const __half* __restrict__ A, const __half* __restrict__ B,
              const float* __restrict__ bias,
              float* __restrict__ Cf, __half* __restrict__ Ch,
              int K, int ldc,
              long long sA, long long sB, long long sC, long long sBias, float alpha)
{
    extern __shared__ char smem[];
    const uint32_t sbase = smem_u32(smem);
    const int tid  = threadIdx.x;
    const int wid  = tid >> 5;
    const int lane = tid & 31;
    const int wy = wid >> 1;            // 0..3  (m, 32 rows each)
    const int wx = wid & 1;             // 0..1  (n, 64 cols each)
    const int m0 = blockIdx.y * BMm;
    const int n0 = blockIdx.x * BNm;
    A += (long long)blockIdx.z * sA;
    B += (long long)blockIdx.z * sB;
    if (BIASMODE) bias += (long long)blockIdx.z * sBias;

    float acc[2][8][4];
#pragma unroll
    for (int i = 0; i < 2; i++)
#pragma unroll
        for (int j = 0; j < 8; j++)
#pragma unroll
            for (int q = 0; q < 4; q++) acc[i][j][q] = 0.0f;

    const int nch = K / BKm;

    // hoisted per-thread gmem pointers and smem store offset for cp.async
    const int rA = tid >> 3, cA = tid & 7;
    const __half* gA = A + (long long)(m0 + rA) * K + cA * 8;
    const __half* gB = B + (long long)(n0 + rA) * K + cA * 8;
    const uint32_t soff = (uint32_t)(rA * LDSm + cA * 8) * 2;
    const long long gstep = (long long)32 * K;                 // 32 rows

    // full-stage load (prologue only)
    auto load_stage = [&](uint32_t sb, int k0) {
#pragma unroll
        for (int t = 0; t < 4; t++)
            CP16(sb + soff + t * (32 * LDSm * 2), gA + t * gstep + k0);
#pragma unroll
        for (int t = 0; t < 4; t++)
            CP16(sb + OPA + soff + t * (32 * LDSm * 2), gB + t * gstep + k0);
    };

    // 1/8th of a stage load; p in [0,8)
    auto load_part = [&](uint32_t sb, int k0, int p) {
        if (p < 4)
            CP16(sb + soff + p * (32 * LDSm * 2), gA + p * gstep + k0);
        else
            CP16(sb + OPA + soff + (p - 4) * (32 * LDSm * 2), gB + (p - 4) * gstep + k0);
    };

    load_stage(sbase, 0);           CP_COMMIT();
    load_stage(sbase + STGB, BKm);  CP_COMMIT();

    // ldmatrix lane base addresses (smem-stage-relative)
    const int arow = (lane & 7) + ((lane >> 3) & 1) * 8;   // 0..15
    const int acol = (lane >> 4) * 8;                      // 0 / 8
    const int brow = (lane & 7) + (lane >> 4) * 8;
    const int bcol = ((lane >> 3) & 1) * 8;
    const uint32_t baseA = (uint32_t)((32 * wy + arow) * LDSm + acol) * 2;
    const uint32_t baseB = (uint32_t)((64 * wx + brow) * LDSm + bcol) * 2 + OPA;

    uint32_t af[2][2][4];      // A fragments, double buffered over ks
    uint32_t bf[2][4][2];      // B fragments, rolling buffer per half-ks (4 j each)

    auto ldA = [&](int buf, uint32_t sb, int ks) {
#pragma unroll
        for (int i = 0; i < 2; i++) {
            uint32_t aoff = sb + baseA + (uint32_t)(16 * i * LDSm + ks * 16) * 2;
            LDSM4(af[buf][i][0], af[buf][i][1], af[buf][i][2], af[buf][i][3], aoff);
        }
    };
    auto ldB = [&](int buf, uint32_t sb, int ks, int jh) {
#pragma unroll
        for (int jpp = 0; jpp < 2; jpp++) {
            uint32_t boff = sb + baseB
                          + (uint32_t)(16 * (2 * jh + jpp) * LDSm + ks * 16) * 2;
            LDSM4(bf[buf][2*jpp][0], bf[buf][2*jpp][1], bf[buf][2*jpp+1][0], bf[buf][2*jpp+1][1],
                  boff);
        }
    };

    uint32_t sb_cur = sbase;                  // stage for chunk c
    uint32_t sb_pf  = sbase + 2 * STGB;       // stage for chunk c+2
    int k_pf = 2 * BKm;                       // k0 for chunk c+2

    for (int c = 0; c < nch; c++) {
        CP_WAIT1();
        __syncthreads();
        const uint32_t sb = sb_cur;
        const bool pf = (c + 2 < nch);
        const uint32_t s2 = sb_pf;
        const int k2 = k_pf;

        ldA(0, sb, 0);
        ldB(0, sb, 0, 0);
#pragma unroll
        for (int idx = 0; idx < 8; idx++) {          // ks = idx>>1, jh = idx&1
            const int ks = idx >> 1, jh = idx & 1;
            if (idx < 7) ldB((idx + 1) & 1, sb, (idx + 1) >> 1, (idx + 1) & 1);
            if (jh == 0 && ks < 3) ldA((ks + 1) & 1, sb, ks + 1);
            if (pf) load_part(s2, k2, idx);
            const int ab = ks & 1, bb = idx & 1;
#pragma unroll
            for (int i = 0; i < 2; i++)
#pragma unroll
                for (int jj = 0; jj < 4; jj++)
                    MMAH(acc[i][jh * 4 + jj],
                         af[ab][i][0], af[ab][i][1], af[ab][i][2], af[ab][i][3],
                         bf[bb][jj][0], bf[bb][jj][1]);
        }
        CP_COMMIT();
        // rotate stage pointers (no modulo)
        sb_cur += STGB; if (sb_cur == sbase + NSTAGE * STGB) sb_cur = sbase;
        sb_pf  += STGB; if (sb_pf  == sbase + NSTAGE * STGB) sb_pf  = sbase;
        k_pf   += BKm;
    }

    // ------------------------------ epilogue --------------------------------
    const int g  = lane >> 2;
    const int t4 = lane & 3;
    const long long cb = (long long)blockIdx.z * sC;
#pragma unroll
    for (int i = 0; i < 2; i++) {
#pragma unroll
        for (int j = 0; j < 8; j++) {
            int mrow = m0 + 32 * wy + 16 * i + g;
            int ncol = n0 + 64 * wx + 8 * j + 2 * t4;
            float v00 = acc[i][j][0] * alpha, v01 = acc[i][j][1] * alpha;
            float v10 = acc[i][j][2] * alpha, v11 = acc[i][j][3] * alpha;
            long long o0 = cb + (long long)mrow * ldc + ncol;
            long long o1 = cb + (long long)(mrow + 8) * ldc + ncol;
            if (BIASMODE == 1) {
                float b0 = bias[ncol], b1 = bias[ncol + 1];
                v00 += b0; v01 += b1; v10 += b0; v11 += b1;
            } else if (BIASMODE == 2) {
                float br0 = bias[mrow], br1 = bias[mrow + 8];
                v00 += br0; v01 += br0; v10 += br1; v11 += br1;
            }
            if (EPI == 0) {
                *(float2*)(Cf + o0) = make_float2(v00, v01);
                *(float2*)(Cf + o1) = make_float2(v10, v11);
            } else {
                *(__half2*)(Ch + o0) = __floats2half2_rn(v00, v01);
                *(__half2*)(Ch + o1) = __floats2half2_rn(v10, v11);
            }
        }
    }
}

// --------------------------- aux kernels ------------------------------------
// fp32 -> fp16 AND copy x into out[:, 0:D] (concat first half)
__global__ void cvt_x(const float* __restrict__ in, __half* __restrict__ out16,
                      float* __restrict__ outx)
{
    long long i = ((long long)blockIdx.x * blockDim.x + threadIdx.x) * 4;
    float4 v = *(const float4*)(in + i);
    *(__half2*)(out16 + i)     = __floats2half2_rn(v.x, v.y);
    *(__half2*)(out16 + i + 2) = __floats2half2_rn(v.z, v.w);
    long long row = i >> 10;              // / Dd
    long long col = i & (Dd - 1);
    *(float4*)(outx + row * (2 * Dd) + col) = v;
}

__global__ void copy_bias(const float* __restrict__ b0, const float* __restrict__ b1,
                          float* __restrict__ dst)
{
    int z = blockIdx.x;
    const float* s = (z == 0) ? b0 : b1;
    dst[z * Dd + threadIdx.x] = s[threadIdx.x];
}

// Wt[n,k] = W[k,n] fp16 ; z selects which W
__global__ void transW(const float* __restrict__ W0, const float* __restrict__ W1,
                       const float* __restrict__ W2, __half* __restrict__ out)
{
    __shared__ float t[32][33];
    const float* W = (blockIdx.z == 0) ? W0 : (blockIdx.z == 1) ? W1 : W2;
    __half* o = out + (size_t)blockIdx.z * Dd * Dd;
    int bx = blockIdx.x * 32, by = blockIdx.y * 32;
    int tx = threadIdx.x, ty = threadIdx.y;
#pragma unroll
    for (int r = 0; r < 4; r++)
        t[ty + 8 * r][tx] = W[(long long)(by + ty + 8 * r) * Dd + bx + tx];
    __syncthreads();
#pragma unroll
    for (int r = 0; r < 4; r++)
        o[(long long)(bx + ty + 8 * r) * Dd + by + tx] = __float2half_rn(t[tx][ty + 8 * r]);
}

// softmax: reads raw fp16 scores, computes fp32, writes fp32 weight + fp16 copy
__global__ void softmax_split(const __half* __restrict__ S, float* __restrict__ W,
                              __half* __restrict__ wh)
{
    long long row = blockIdx.x;
    const __half* ps = S + row * (long long)Nn;
    float* p = W + row * (long long)Nn;
    __half* ph = wh + row * (long long)Nn;
    __shared__ float red[8];
    const int tid = threadIdx.x;
    const int lane = tid & 31, warp = tid >> 5;

    float e[8];
    {
        uint4 raw = *(const uint4*)(ps + tid * 8);     // 8 halves
        __half2 h0 = *(__half2*)&raw.x;
        __half2 h1 = *(__half2*)&raw.y;
        __half2 h2 = *(__half2*)&raw.z;
        __half2 h3 = *(__half2*)&raw.w;
        float2 f0 = __half22float2(h0), f1 = __half22float2(h1);
        float2 f2 = __half22float2(h2), f3 = __half22float2(h3);
        e[0]=f0.x; e[1]=f0.y; e[2]=f1.x; e[3]=f1.y;
        e[4]=f2.x; e[5]=f2.y; e[6]=f3.x; e[7]=f3.y;
    }
    float mx = e[0];
#pragma unroll
    for (int i = 1; i < 8; i++) mx = fmaxf(mx, e[i]);
#pragma unroll
    for (int s = 16; s > 0; s >>= 1)
        mx = fmaxf(mx, __shfl_xor_sync(0xffffffffu, mx, s));
    if (lane == 0) red[warp] = mx;
    __syncthreads();
    mx = red[0];
#pragma unroll
    for (int w = 1; w < 8; w++) mx = fmaxf(mx, red[w]);
    __syncthreads();

    float sum = 0.0f;
#pragma unroll
    for (int i = 0; i < 8; i++) { e[i] = expf(e[i] - mx); sum += e[i]; }
#pragma unroll
    for (int s = 16; s > 0; s >>= 1)
        sum += __shfl_xor_sync(0xffffffffu, sum, s);
    if (lane == 0) red[warp] = sum;
    __syncthreads();
    sum = red[0];
#pragma unroll
    for (int w = 1; w < 8; w++) sum += red[w];
    float inv = 1.0f / sum;

    float4 o0, o1;
    o0.x = e[0]*inv; o0.y = e[1]*inv; o0.z = e[2]*inv; o0.w = e[3]*inv;
    o1.x = e[4]*inv; o1.y = e[5]*inv; o1.z = e[6]*inv; o1.w = e[7]*inv;
    *(float4*)(p + tid * 8)     = o0;
    *(float4*)(p + tid * 8 + 4) = o1;
    *(__half2*)(ph + tid * 8)     = __floats2half2_rn(o0.x, o0.y);
    *(__half2*)(ph + tid * 8 + 2) = __floats2half2_rn(o0.z, o0.w);
    *(__half2*)(ph + tid * 8 + 4) = __floats2half2_rn(o1.x, o1.y);
    *(__half2*)(ph + tid * 8 + 6) = __floats2half2_rn(o1.z, o1.w);
}

// residual + layernorm (warp-shuffle reductions, float4 I/O); writes out[:, D:2D]
__global__ void ln_concat(const float* __restrict__ x, const float* __restrict__ att,
                          const float* __restrict__ gamma, const float* __restrict__ beta,
                          float* __restrict__ out)
{
    long long row = blockIdx.x;
    const float* xr = x + row * Dd;
    const float* ar = att + row * Dd;
    float* o = out + row * (2 * Dd);
    __shared__ float red[8];
    const int tid = threadIdx.x;
    const int lane = tid & 31, warp = tid >> 5;
    const int c0 = tid * 4;

    float4 xv = *(const float4*)(xr + c0);
    float4 av = *(const float4*)(ar + c0);
    float h[4] = {xv.x + av.x, xv.y + av.y, xv.z + av.z, xv.w + av.w};
    float s = h[0] + h[1] + h[2] + h[3];
#pragma unroll
    for (int st = 16; st > 0; st >>= 1)
        s += __shfl_xor_sync(0xffffffffu, s, st);
    if (lane == 0) red[warp] = s;
    __syncthreads();
    s = red[0];
#pragma unroll
    for (int w = 1; w < 8; w++) s += red[w];
    float mu = s * (1.0f / Dd);
    __syncthreads();

    float v = 0.0f;
#pragma unroll
    for (int i = 0; i < 4; i++) { float d = h[i] - mu; v += d * d; }
#pragma unroll
    for (int st = 16; st > 0; st >>= 1)
        v += __shfl_xor_sync(0xffffffffu, v, st);
    if (lane == 0) red[warp] = v;
    __syncthreads();
    v = red[0];
#pragma unroll
    for (int w = 1; w < 8; w++) v += red[w];
    float rstd = rsqrtf(v * (1.0f / Dd) + 1e-5f);

    float4 gv = *(const float4*)(gamma + c0);
    float4 bv = *(const float4*)(beta + c0);
    float4 ov;
    ov.x = (h[0] - mu) * rstd * gv.x + bv.x;
    ov.y = (h[1] - mu) * rstd * gv.y + bv.y;
    ov.z = (h[2] - mu) * rstd * gv.z + bv.z;
    ov.w = (h[3] - mu) * rstd * gv.w + bv.w;
    *(float4*)(o + Dd + c0) = ov;
}

// ------------------------------- launcher -----------------------------------
extern "C" void kernel_launch(void* const* d_in, const int* in_sizes, int n_in,
                              void* d_out, int out_size)
{
    const float* x     = (const float*)d_in[0];
    const float* Wk    = (const float*)d_in[1];
    const float* bk    = (const float*)d_in[2];
    const float* Wq    = (const float*)d_in[3];
    const float* bq    = (const float*)d_in[4];
    const float* Wv    = (const float*)d_in[5];
    const float* bv    = (const float*)d_in[6];
    const float* gamma = (const float*)d_in[7];
    const float* beta  = (const float*)d_in[8];

    float* out = (float*)d_out;
    float* att = out + (long long)MT * 2 * Dd;
    float* wgt = att + (long long)MT * Dd;

    __half *x16, *W16, *QK, *Vt, *s16, *w16;
    float* bqk;
    cudaGetSymbolAddress((void**)&x16, g_x16);
    cudaGetSymbolAddress((void**)&W16, g_W16);
    cudaGetSymbolAddress((void**)&bqk, g_b);
    cudaGetSymbolAddress((void**)&QK,  g_QK);
    cudaGetSymbolAddress((void**)&Vt,  g_Vt);
    cudaGetSymbolAddress((void**)&s16, g_s16);
    cudaGetSymbolAddress((void**)&w16, g_w16);

    cudaFuncSetAttribute(mma_gemm<0, 0>, cudaFuncAttributeMaxDynamicSharedMemorySize, SMEM_BYTES);
    cudaFuncSetAttribute(mma_gemm<1, 0>, cudaFuncAttributeMaxDynamicSharedMemorySize, SMEM_BYTES);
    cudaFuncSetAttribute(mma_gemm<1, 1>, cudaFuncAttributeMaxDynamicSharedMemorySize, SMEM_BYTES);
    cudaFuncSetAttribute(mma_gemm<1, 2>, cudaFuncAttributeMaxDynamicSharedMemorySize, SMEM_BYTES);

    cudaStream_t s1 = g_ss.s1, s2 = g_ss.s2, s3 = g_ss.s3;

    const size_t halfX = (size_t)2 * Nn * Dd;     // 2 batches of x/Q/K rows
    const long long sQK = (long long)Nn * Dd;     // per-batch stride Q/K/att/Vt
    const long long sW  = (long long)Nn * Nn;     // per-batch stride scores

    // per-batch chain: scores -> softmax -> attn -> ln (batch b on stream st)
    auto chain = [&](cudaStream_t st, int b) {
        {
            dim3 g(Nn / BNm, Nn / BMm, 1), blk(256);
            mma_gemm<1, 0><<<g, blk, SMEM_BYTES, st>>>(
                QK + b * sQK, QK + (size_t)MT * Dd + b * sQK, nullptr,
                nullptr, s16 + b * sW,
                Dd, Nn, 0, 0, 0, 0, 1.0f / 32.0f);
        }
        softmax_split<<<Nn, 256, 0, st>>>(s16 + b * sW, wgt + b * sW, w16 + b * sW);
        cudaStreamWaitEvent(st, g_ss.eV, 0);
        {
            dim3 g(Dd / BNm, Nn / BMm, 1), blk(256);
            mma_gemm<0, 0><<<g, blk, SMEM_BYTES, st>>>(
                w16 + b * sW, Vt + b * sQK, nullptr,
                att + b * sQK, nullptr,
                Nn, Dd, 0, 0, 0, 0, 1.0f);
        }
        ln_concat<<<Nn, 256, 0, st>>>(x + (size_t)b * Nn * Dd, att + b * sQK,
                                      gamma, beta, out + (size_t)b * Nn * 2 * Dd);
    };

    // ---- fork side streams from origin ----
    cudaEventRecord(g_ss.e0, 0);
    cudaStreamWaitEvent(s1, g_ss.e0, 0);
    cudaStreamWaitEvent(s2, g_ss.e0, 0);
    cudaStreamWaitEvent(s3, g_ss.e0, 0);

    // s1: bias pack + weight transposes
    copy_bias<<<2, Dd, 0, s1>>>(bq, bk, bqk);
    {
        dim3 g(Dd / 32, Dd / 32, 3), b(32, 8);
        transW<<<g, b, 0, s1>>>(Wq, Wk, Wv, W16);
    }
    cudaEventRecord(g_ss.eW, s1);

    // s3: cvt half B (batches 2,3)
    cvt_x<<<1024, 1024, 0, s3>>>(x + halfX, x16 + halfX,
                                 out + (size_t)2 * Nn * 2 * Dd);
    cudaEventRecord(g_ss.e1b, s3);

    // main: cvt half A (batches 0,1)
    cvt_x<<<1024, 1024>>>(x, x16, out);
    cudaEventRecord(g_ss.e1a, 0);

    // s1: Vt = Wv^T @ x^T + bv (per batch; needs full x16 + W16)
    cudaStreamWaitEvent(s1, g_ss.e1a, 0);
    cudaStreamWaitEvent(s1, g_ss.e1b, 0);
    {
        dim3 g(Nn / BNm, Dd / BMm, Bb), b(256);
        mma_gemm<1, 2><<<g, b, SMEM_BYTES, s1>>>(W16 + (size_t)2 * Dd * Dd, x16, bv,
                                                 nullptr, Vt,
                                                 Dd, Nn,
                                                 0, sQK, (long long)Dd * Nn, 0, 1.0f);
    }
    cudaEventRecord(g_ss.eV, s1);

    // main: QK projection half A (batches 0,1)
    cudaStreamWaitEvent(0, g_ss.eW, 0);
    {
        dim3 g(Dd / BNm, 32, 2), b(256);
        mma_gemm<1, 1><<<g, b, SMEM_BYTES>>>(x16, W16, bqk, nullptr, QK,
                                             Dd, Dd,
                                             0, (long long)Dd * Dd, (long long)MT * Dd,
                                             Dd, 1.0f);
    }
    cudaEventRecord(g_ss.eQA, 0);

    // main: QK projection half B (batches 2,3) — needs x16 half B
    cudaStreamWaitEvent(0, g_ss.e1b, 0);
    {
        dim3 g(Dd / BNm, 32, 2), b(256);
        mma_gemm<1, 1><<<g, b, SMEM_BYTES>>>(x16 + halfX, W16, bqk, nullptr, QK + halfX,
                                             Dd, Dd,
                                             0, (long long)Dd * Dd, (long long)MT * Dd,
                                             Dd, 1.0f);
    }
    cudaEventRecord(g_ss.eQB, 0);

    // s2: batch-0 chain ; s3: batch-1 chain (both need QK half A)
    cudaStreamWaitEvent(s2, g_ss.eQA, 0);
    chain(s2, 0);
    cudaEventRecord(g_ss.eL0, s2);

    cudaStreamWaitEvent(s3, g_ss.eQA, 0);
    chain(s3, 1);
    cudaEventRecord(g_ss.eL1, s3);

    // s1: batch-3 chain (after Vt; needs QK half B)
    cudaStreamWaitEvent(s1, g_ss.eQB, 0);
    chain(s1, 3);
    cudaEventRecord(g_ss.eL3, s1);

    // main: batch-2 chain
    chain(0, 2);

    // join all side chains into origin
    cudaStreamWaitEvent(0, g_ss.eL0, 0);
    cudaStreamWaitEvent(0, g_ss.eL1, 0);
    cudaStreamWaitEvent(0, g_ss.eL3, 0);
}